// round 1
// baseline (speedup 1.0000x reference)
#include <cuda_runtime.h>
#include <cuda_bf16.h>
#include <math.h>

// Problem constants (fixed by the reference)
#define BB   2
#define LL   2048
#define DD   1024
#define HH   16
#define KVH  4
#define HDIM 64
#define GRP  (HH / KVH)   // 4
#define BL   (BB * LL)    // 4096

// ---------------------------------------------------------------------------
// Scratch (no allocations allowed -> __device__ globals)
// ---------------------------------------------------------------------------
__device__ float g_q[BL * HH * HDIM];      // [4096][1024]  16MB
__device__ float g_k[BL * KVH * HDIM];     // [4096][256]    4MB
__device__ float g_v[BL * KVH * HDIM];     // [4096][256]    4MB
__device__ float g_ctx[BL * HH * HDIM];    // [4096][1024]  16MB

// ---------------------------------------------------------------------------
// SGEMM: C[M,N] = A[M,K] @ B[K,N], row-major, M,N multiples of 64, K of 16
// 64x64 tile, BK=16, 256 threads, 4x4 microtile
// ---------------------------------------------------------------------------
__global__ __launch_bounds__(256)
void sgemm64(const float* __restrict__ A, const float* __restrict__ B,
             float* __restrict__ C, int M, int N, int K) {
    __shared__ float As[16][65];   // padded: conflict-free transposed stores
    __shared__ float Bs[16][64];

    const int tid  = threadIdx.x;
    const int tx   = tid & 15;
    const int ty   = tid >> 4;
    const int row0 = blockIdx.y * 64;
    const int col0 = blockIdx.x * 64;

    const int ar = tid >> 2;             // A row within tile  (0..63)
    const int ak = (tid & 3) << 2;       // A k within tile    (0,4,8,12)
    const int bk = tid >> 4;             // B k within tile    (0..15)
    const int bc = (tid & 15) << 2;      // B col within tile

    float acc[4][4] = {};

    for (int k0 = 0; k0 < K; k0 += 16) {
        float4 a  = *reinterpret_cast<const float4*>(
            A + (size_t)(row0 + ar) * K + k0 + ak);
        float4 bv = *reinterpret_cast<const float4*>(
            B + (size_t)(k0 + bk) * N + col0 + bc);

        As[ak + 0][ar] = a.x;
        As[ak + 1][ar] = a.y;
        As[ak + 2][ar] = a.z;
        As[ak + 3][ar] = a.w;
        *reinterpret_cast<float4*>(&Bs[bk][bc]) = bv;
        __syncthreads();

#pragma unroll
        for (int k = 0; k < 16; k++) {
            float  arv[4];
            float4 brv = *reinterpret_cast<const float4*>(&Bs[k][tx << 2]);
#pragma unroll
            for (int i = 0; i < 4; i++) arv[i] = As[k][(ty << 2) + i];
            float br[4] = {brv.x, brv.y, brv.z, brv.w};
#pragma unroll
            for (int i = 0; i < 4; i++)
#pragma unroll
                for (int j = 0; j < 4; j++) acc[i][j] += arv[i] * br[j];
        }
        __syncthreads();
    }

#pragma unroll
    for (int i = 0; i < 4; i++) {
        float4 c4 = make_float4(acc[i][0], acc[i][1], acc[i][2], acc[i][3]);
        *reinterpret_cast<float4*>(
            C + (size_t)(row0 + (ty << 2) + i) * N + col0 + (tx << 2)) = c4;
    }
}

// ---------------------------------------------------------------------------
// RoPE in-place on g_q ([BL][H*64]) and g_k ([BL][KV*64])
// thread handles one (pos, head, j) pair: dims j and j+32
// ---------------------------------------------------------------------------
__global__ __launch_bounds__(256)
void rope_kernel(float* __restrict__ q, float* __restrict__ k) {
    const int TQ = BL * HH * 32;   // 2,097,152
    const int TK = BL * KVH * 32;  //   524,288
    int idx = blockIdx.x * 256 + threadIdx.x;
    float* base;
    int j, pos;
    if (idx < TQ) {
        j = idx & 31;
        int t  = idx >> 5;       // (b*L+l)*H + h
        int bl = t >> 4;
        pos = bl & (LL - 1);
        base = q + ((size_t)t << 6);
    } else if (idx < TQ + TK) {
        int id2 = idx - TQ;
        j = id2 & 31;
        int t  = id2 >> 5;       // (b*L+l)*KV + kv
        int bl = t >> 2;
        pos = bl & (LL - 1);
        base = k + ((size_t)t << 6);
    } else {
        return;
    }
    float inv = powf(10000.0f, -(float)j * (1.0f / 32.0f));
    float ang = (float)pos * inv;
    float s, c;
    sincosf(ang, &s, &c);
    float x1 = base[j];
    float x2 = base[j + 32];
    base[j]      = x1 * c - x2 * s;
    base[j + 32] = x2 * c + x1 * s;
}

// ---------------------------------------------------------------------------
// Flash attention with ALiBi, full (non-causal) softmax, GQA (kv = h/4)
// grid: (L/64, H, B); 256 threads; thread = (row = tid>>2, quarter = tid&3)
// dynamic smem: Qs,Ks,Vs,Ps each 64x65 floats
// ---------------------------------------------------------------------------
__global__ __launch_bounds__(256)
void attn_kernel(const float* __restrict__ Q, const float* __restrict__ K,
                 const float* __restrict__ V, float* __restrict__ ctx) {
    extern __shared__ float sm[];
    float* Qs = sm;                  // 64*65
    float* Ks = Qs + 64 * 65;
    float* Vs = Ks + 64 * 65;
    float* Ps = Vs + 64 * 65;

    const int q0  = blockIdx.x * 64;
    const int h   = blockIdx.y;
    const int b   = blockIdx.z;
    const int kvh = h >> 2;          // h / GROUPS
    const int tid = threadIdx.x;
    const int row = tid >> 2;        // 0..63
    const int qtr = tid & 3;         // 0..3

    const float slope = exp2f(-0.5f * (float)(h + 1));
    const float scale = 0.125f;      // 1/sqrt(64)

    // load Q tile
    for (int i = tid; i < 64 * 64; i += 256) {
        int r = i >> 6, d = i & 63;
        Qs[r * 65 + d] =
            Q[((size_t)(b * LL + q0 + r)) * (HH * HDIM) + h * HDIM + d];
    }

    float o[16];
#pragma unroll
    for (int i = 0; i < 16; i++) o[i] = 0.0f;
    float m = -1e30f, lsum = 0.0f;

    for (int k0 = 0; k0 < LL; k0 += 64) {
        __syncthreads();  // covers Q load (iter 0) + K/V/P reuse (iter>0)
        for (int i = tid; i < 64 * 64; i += 256) {
            int r = i >> 6, d = i & 63;
            size_t g =
                ((size_t)(b * LL + k0 + r)) * (KVH * HDIM) + kvh * HDIM + d;
            Ks[r * 65 + d] = K[g];
            Vs[r * 65 + d] = V[g];
        }
        __syncthreads();

        // S = Q . K^T  (16 keys per thread)
        float s[16];
#pragma unroll
        for (int j = 0; j < 16; j++) s[j] = 0.0f;
        const float* qrow = Qs + row * 65;
#pragma unroll 4
        for (int d0 = 0; d0 < 64; d0 += 4) {
            float qa = qrow[d0], qb = qrow[d0 + 1];
            float qc = qrow[d0 + 2], qd = qrow[d0 + 3];
#pragma unroll
            for (int j = 0; j < 16; j++) {
                const float* kr = Ks + (qtr * 16 + j) * 65 + d0;
                s[j] += qa * kr[0] + qb * kr[1] + qc * kr[2] + qd * kr[3];
            }
        }

        // scale + ALiBi bias + local max
        float mloc = -1e30f;
#pragma unroll
        for (int j = 0; j < 16; j++) {
            int kc = k0 + qtr * 16 + j;
            s[j] = s[j] * scale + slope * (float)(kc - (q0 + row));
            mloc = fmaxf(mloc, s[j]);
        }
        // row max across the 4 quarter-threads (same row = tid>>2)
        mloc = fmaxf(mloc, __shfl_xor_sync(0xffffffffu, mloc, 1));
        mloc = fmaxf(mloc, __shfl_xor_sync(0xffffffffu, mloc, 2));
        float mnew = fmaxf(m, mloc);
        float corr = __expf(m - mnew);

        float psum = 0.0f;
#pragma unroll
        for (int j = 0; j < 16; j++) {
            float p = __expf(s[j] - mnew);
            Ps[row * 65 + qtr * 16 + j] = p;
            psum += p;
        }
        psum += __shfl_xor_sync(0xffffffffu, psum, 1);
        psum += __shfl_xor_sync(0xffffffffu, psum, 2);
        lsum = lsum * corr + psum;
        m = mnew;
#pragma unroll
        for (int i = 0; i < 16; i++) o[i] *= corr;
        __syncthreads();

        // O += P @ V  (thread owns row, dims qtr*16..+15)
        const float* prow = Ps + row * 65;
        const float* vb   = Vs + qtr * 16;
#pragma unroll 4
        for (int kc = 0; kc < 64; kc++) {
            float p = prow[kc];
            const float* vrow = vb + kc * 65;
#pragma unroll
            for (int i = 0; i < 16; i++) o[i] += p * vrow[i];
        }
    }

    float inv_l = 1.0f / lsum;
    size_t base =
        ((size_t)(b * LL + q0 + row)) * (HH * HDIM) + h * HDIM + qtr * 16;
#pragma unroll
    for (int i = 0; i < 16; i++) ctx[base + i] = o[i] * inv_l;
}

// ---------------------------------------------------------------------------
// kernel_launch
// ---------------------------------------------------------------------------
extern "C" void kernel_launch(void* const* d_in, const int* in_sizes, int n_in,
                              void* d_out, int out_size) {
    const float* x  = (const float*)d_in[0];
    const float* Wq = (const float*)d_in[1];
    const float* Wk = (const float*)d_in[2];
    const float* Wv = (const float*)d_in[3];
    const float* Wo = (const float*)d_in[4];
    float* out = (float*)d_out;

    float *pq, *pk, *pv, *pctx;
    cudaGetSymbolAddress((void**)&pq,   g_q);
    cudaGetSymbolAddress((void**)&pk,   g_k);
    cudaGetSymbolAddress((void**)&pv,   g_v);
    cudaGetSymbolAddress((void**)&pctx, g_ctx);

    const int smem_attn = 4 * 64 * 65 * (int)sizeof(float);  // 66560
    cudaFuncSetAttribute(attn_kernel,
                         cudaFuncAttributeMaxDynamicSharedMemorySize,
                         smem_attn);

    dim3 blk(256);

    // QKV projections
    sgemm64<<<dim3(HH * HDIM / 64, BL / 64), blk>>>(x, Wq, pq, BL, HH * HDIM, DD);
    sgemm64<<<dim3(KVH * HDIM / 64, BL / 64), blk>>>(x, Wk, pk, BL, KVH * HDIM, DD);
    sgemm64<<<dim3(KVH * HDIM / 64, BL / 64), blk>>>(x, Wv, pv, BL, KVH * HDIM, DD);

    // RoPE on q and k
    {
        int total = BL * (HH + KVH) * 32;
        rope_kernel<<<(total + 255) / 256, blk>>>(pq, pk);
    }

    // attention
    attn_kernel<<<dim3(LL / 64, HH, BB), blk, smem_attn>>>(pq, pk, pv, pctx);

    // output projection
    sgemm64<<<dim3(DD / 64, BL / 64), blk>>>(pctx, Wo, out, BL, DD, DD);
}

// round 2
// speedup vs baseline: 2.9127x; 2.9127x over previous
#include <cuda_runtime.h>
#include <math.h>

// Problem constants (fixed by the reference)
#define BB   2
#define LL   2048
#define DD   1024
#define HH   16
#define KVH  4
#define HDIM 64
#define BL   (BB * LL)    // 4096

typedef unsigned long long ull;

// ---------------------------------------------------------------------------
// packed f32x2 helpers (sm_103a: FFMA rt=2, f32x2 doubles FMA/issue)
// ---------------------------------------------------------------------------
__device__ __forceinline__ ull pack2(float x, float y) {
    ull r; asm("mov.b64 %0, {%1,%2};" : "=l"(r) : "f"(x), "f"(y)); return r;
}
__device__ __forceinline__ void unpack2(ull v, float& x, float& y) {
    asm("mov.b64 {%0,%1}, %2;" : "=f"(x), "=f"(y) : "l"(v));
}
__device__ __forceinline__ ull ffma2(ull a, ull b, ull c) {
    ull d; asm("fma.rn.f32x2 %0, %1, %2, %3;" : "=l"(d) : "l"(a), "l"(b), "l"(c));
    return d;
}
__device__ __forceinline__ ull fmul2(ull a, ull b) {
    ull d; asm("mul.rn.f32x2 %0, %1, %2;" : "=l"(d) : "l"(a), "l"(b));
    return d;
}

// ---------------------------------------------------------------------------
// Scratch (no allocations allowed -> __device__ globals)
// ---------------------------------------------------------------------------
__device__ float g_q[BL * HH * HDIM];
__device__ float g_k[BL * KVH * HDIM];
__device__ float g_v[BL * KVH * HDIM];
__device__ float g_ctx[BL * HH * HDIM];

// ---------------------------------------------------------------------------
// SGEMM: C[M,N] = A[M,K] @ B[K,N]. 128x128x16 tile, 256 thr, 8x8 microtile,
// packed f32x2 accumulation. M,N mult of 128, K mult of 16.
// ---------------------------------------------------------------------------
__global__ __launch_bounds__(256, 2)
void sgemm128(const float* __restrict__ A, const float* __restrict__ B,
              float* __restrict__ C, int M, int N, int K) {
    __shared__ float As[16][132];   // [k][m] transposed, padded
    __shared__ float Bs[16][128];   // [k][n]

    const int tid  = threadIdx.x;
    const int tx   = tid & 15;
    const int ty   = tid >> 4;
    const int row0 = blockIdx.y << 7;
    const int col0 = blockIdx.x << 7;

    const int ar = tid >> 1;            // 0..127
    const int ak = (tid & 1) << 3;      // 0 or 8
    const int bk = ty;                  // 0..15
    const int bc = tx << 3;             // 0..120

    const float* Aptr = A + (size_t)(row0 + ar) * K + ak;
    const float* Bptr = B + (size_t)bk * N + col0 + bc;

    ull acc[8][4];
#pragma unroll
    for (int i = 0; i < 8; i++)
#pragma unroll
        for (int j = 0; j < 4; j++) acc[i][j] = 0ull;

    for (int k0 = 0; k0 < K; k0 += 16) {
        float4 a0 = *(const float4*)(Aptr + k0);
        float4 a1 = *(const float4*)(Aptr + k0 + 4);
        float4 b0 = *(const float4*)(Bptr + (size_t)k0 * N);
        float4 b1 = *(const float4*)(Bptr + (size_t)k0 * N + 4);
        __syncthreads();
        As[ak + 0][ar] = a0.x; As[ak + 1][ar] = a0.y;
        As[ak + 2][ar] = a0.z; As[ak + 3][ar] = a0.w;
        As[ak + 4][ar] = a1.x; As[ak + 5][ar] = a1.y;
        As[ak + 6][ar] = a1.z; As[ak + 7][ar] = a1.w;
        *(float4*)&Bs[bk][bc]     = b0;
        *(float4*)&Bs[bk][bc + 4] = b1;
        __syncthreads();

#pragma unroll
        for (int k = 0; k < 16; k++) {
            float4 al = *(const float4*)&As[k][ty << 3];       // broadcast
            float4 ah = *(const float4*)&As[k][(ty << 3) + 4];
            ulonglong2 bl = *(const ulonglong2*)&Bs[k][tx << 3];
            ulonglong2 bh = *(const ulonglong2*)&Bs[k][(tx << 3) + 4];
            ull bj0 = bl.x, bj1 = bl.y, bj2 = bh.x, bj3 = bh.y;
            float av[8] = {al.x, al.y, al.z, al.w, ah.x, ah.y, ah.z, ah.w};
#pragma unroll
            for (int i = 0; i < 8; i++) {
                ull ap = pack2(av[i], av[i]);
                acc[i][0] = ffma2(ap, bj0, acc[i][0]);
                acc[i][1] = ffma2(ap, bj1, acc[i][1]);
                acc[i][2] = ffma2(ap, bj2, acc[i][2]);
                acc[i][3] = ffma2(ap, bj3, acc[i][3]);
            }
        }
    }

#pragma unroll
    for (int i = 0; i < 8; i++) {
        ulonglong2* dst = (ulonglong2*)(
            C + (size_t)(row0 + (ty << 3) + i) * N + col0 + (tx << 3));
        ulonglong2 w0; w0.x = acc[i][0]; w0.y = acc[i][1];
        ulonglong2 w1; w1.x = acc[i][2]; w1.y = acc[i][3];
        dst[0] = w0;
        dst[1] = w1;
    }
}

// ---------------------------------------------------------------------------
// RoPE in-place on g_q and g_k (unchanged; 12us)
// ---------------------------------------------------------------------------
__global__ __launch_bounds__(256)
void rope_kernel(float* __restrict__ q, float* __restrict__ k) {
    const int TQ = BL * HH * 32;
    const int TK = BL * KVH * 32;
    int idx = blockIdx.x * 256 + threadIdx.x;
    float* base;
    int j, pos;
    if (idx < TQ) {
        j = idx & 31;
        int t  = idx >> 5;
        int bl = t >> 4;
        pos = bl & (LL - 1);
        base = q + ((size_t)t << 6);
    } else if (idx < TQ + TK) {
        int id2 = idx - TQ;
        j = id2 & 31;
        int t  = id2 >> 5;
        int bl = t >> 2;
        pos = bl & (LL - 1);
        base = k + ((size_t)t << 6);
    } else {
        return;
    }
    float inv = powf(10000.0f, -(float)j * (1.0f / 32.0f));
    float ang = (float)pos * inv;
    float s, c;
    sincosf(ang, &s, &c);
    float x1 = base[j];
    float x2 = base[j + 32];
    base[j]      = x1 * c - x2 * s;
    base[j + 32] = x2 * c + x1 * s;
}

// ---------------------------------------------------------------------------
// Flash attention v2: 128q x 128k tiles, 8x8 microtile packed-f32x2 GEMMs.
// grid (L/128, H, B), 256 threads, 160KB dynamic smem (1 CTA/SM).
// Qs/Ks: d-major transposed, XOR-swizzled (bank bits 3..4 ^ (d>>2)&3).
// ---------------------------------------------------------------------------
__global__ __launch_bounds__(256, 1)
void attn2(const float* __restrict__ Qg, const float* __restrict__ Kg,
           const float* __restrict__ Vg, float* __restrict__ ctx) {
    extern __shared__ float sm[];
    float* Qs = sm;                  // [64][128] swizzled
    float* Ks = Qs + 64 * 128;       // [64][128] swizzled
    float* Vs = Ks + 64 * 128;       // [128][64]
    float* Ps = Vs + 128 * 64;       // [128][128]

    const int tid = threadIdx.x;
    const int tx  = tid & 15;
    const int ty  = tid >> 4;
    const int q0  = blockIdx.x << 7;
    const int h   = blockIdx.y;
    const int b   = blockIdx.z;
    const int kvh = h >> 2;

    const float slope = exp2f(-0.5f * (float)(h + 1));
    const float scale = 0.125f;

    // ---- load Q tile, transposed + swizzled ----
    for (int i = tid; i < 2048; i += 256) {
        int r  = i >> 4;
        int d4 = (i & 15) << 2;
        float4 qv = *(const float4*)&Qg[
            (size_t)(b * LL + q0 + r) * (HH * HDIM) + h * HDIM + d4];
        int rs = r ^ (((d4 >> 2) & 3) << 3);
        Qs[(d4 + 0) * 128 + rs] = qv.x;
        Qs[(d4 + 1) * 128 + rs] = qv.y;
        Qs[(d4 + 2) * 128 + rs] = qv.z;
        Qs[(d4 + 3) * 128 + rs] = qv.w;
    }

    ull o[8][2];
    float mrow[8], lrow[8];
#pragma unroll
    for (int i = 0; i < 8; i++) {
        o[i][0] = 0ull; o[i][1] = 0ull;
        mrow[i] = -1e30f; lrow[i] = 0.0f;
    }

    for (int k0 = 0; k0 < LL; k0 += 128) {
        __syncthreads();   // prev PV done before overwriting Ks/Vs (and Q store iter0)
        for (int i = tid; i < 2048; i += 256) {
            int r  = i >> 4;
            int d4 = (i & 15) << 2;
            size_t g = (size_t)(b * LL + k0 + r) * (KVH * HDIM) + kvh * HDIM + d4;
            float4 kv = *(const float4*)&Kg[g];
            float4 vv = *(const float4*)&Vg[g];
            int rs = r ^ (((d4 >> 2) & 3) << 3);
            Ks[(d4 + 0) * 128 + rs] = kv.x;
            Ks[(d4 + 1) * 128 + rs] = kv.y;
            Ks[(d4 + 2) * 128 + rs] = kv.z;
            Ks[(d4 + 3) * 128 + rs] = kv.w;
            *(float4*)&Vs[r * 64 + d4] = vv;
        }
        __syncthreads();

        // ---- S = Q.K^T : 8x8 microtile, packed along key cols ----
        ull s[8][4];
#pragma unroll
        for (int i = 0; i < 8; i++)
#pragma unroll
            for (int j = 0; j < 4; j++) s[i][j] = 0ull;

#pragma unroll 8
        for (int d = 0; d < 64; d++) {
            int sw = ((d >> 2) & 3) << 3;
            const float* qb = Qs + d * 128 + ((ty << 3) ^ sw);
            const float* kb = Ks + d * 128 + ((tx << 3) ^ sw);
            float4 ql = *(const float4*)qb;           // broadcast per ty
            float4 qh = *(const float4*)(qb + 4);
            ulonglong2 kl = *(const ulonglong2*)kb;
            ulonglong2 kh = *(const ulonglong2*)(kb + 4);
            ull b0 = kl.x, b1 = kl.y, b2 = kh.x, b3 = kh.y;
            float qv[8] = {ql.x, ql.y, ql.z, ql.w, qh.x, qh.y, qh.z, qh.w};
#pragma unroll
            for (int i = 0; i < 8; i++) {
                ull ap = pack2(qv[i], qv[i]);
                s[i][0] = ffma2(ap, b0, s[i][0]);
                s[i][1] = ffma2(ap, b1, s[i][1]);
                s[i][2] = ffma2(ap, b2, s[i][2]);
                s[i][3] = ffma2(ap, b3, s[i][3]);
            }
        }

        // ---- online softmax per row (row stats reduced over 16 tx lanes) ----
        const float cbase = (float)(k0 + (tx << 3));
#pragma unroll
        for (int i = 0; i < 8; i++) {
            float sf[8];
            unpack2(s[i][0], sf[0], sf[1]);
            unpack2(s[i][1], sf[2], sf[3]);
            unpack2(s[i][2], sf[4], sf[5]);
            unpack2(s[i][3], sf[6], sf[7]);
            float qpos = (float)(q0 + (ty << 3) + i);
            float bias0 = slope * (cbase - qpos);
#pragma unroll
            for (int j = 0; j < 8; j++)
                sf[j] = fmaf(sf[j], scale, bias0 + slope * (float)j);

            float mx = sf[0];
#pragma unroll
            for (int j = 1; j < 8; j++) mx = fmaxf(mx, sf[j]);
            mx = fmaxf(mx, __shfl_xor_sync(0xffffffffu, mx, 1));
            mx = fmaxf(mx, __shfl_xor_sync(0xffffffffu, mx, 2));
            mx = fmaxf(mx, __shfl_xor_sync(0xffffffffu, mx, 4));
            mx = fmaxf(mx, __shfl_xor_sync(0xffffffffu, mx, 8));

            float mn = fmaxf(mrow[i], mx);
            float c  = __expf(mrow[i] - mn);
            mrow[i]  = mn;

            float p[8], ps = 0.0f;
#pragma unroll
            for (int j = 0; j < 8; j++) {
                p[j] = __expf(sf[j] - mn);
                ps += p[j];
            }
            ps += __shfl_xor_sync(0xffffffffu, ps, 1);
            ps += __shfl_xor_sync(0xffffffffu, ps, 2);
            ps += __shfl_xor_sync(0xffffffffu, ps, 4);
            ps += __shfl_xor_sync(0xffffffffu, ps, 8);
            lrow[i] = lrow[i] * c + ps;

            ull cp = pack2(c, c);
            o[i][0] = fmul2(o[i][0], cp);
            o[i][1] = fmul2(o[i][1], cp);

            float* pd = Ps + ((ty << 3) + i) * 128 + (tx << 3);
            float4 p0; p0.x = p[0]; p0.y = p[1]; p0.z = p[2]; p0.w = p[3];
            float4 p1; p1.x = p[4]; p1.y = p[5]; p1.z = p[6]; p1.w = p[7];
            *(float4*)pd       = p0;
            *(float4*)(pd + 4) = p1;
        }
        __syncthreads();

        // ---- O += P @ V : rows ty*8..+7, dims tx*4..+3 ----
#pragma unroll 4
        for (int kc = 0; kc < 128; kc++) {
            ulonglong2 vv = *(const ulonglong2*)&Vs[kc * 64 + (tx << 2)];
            const float* pc = Ps + (ty << 3) * 128 + kc;
#pragma unroll
            for (int i = 0; i < 8; i++) {
                float pvv = pc[i * 128];     // broadcast per ty
                ull pp = pack2(pvv, pvv);
                o[i][0] = ffma2(pp, vv.x, o[i][0]);
                o[i][1] = ffma2(pp, vv.y, o[i][1]);
            }
        }
    }

    // ---- epilogue ----
#pragma unroll
    for (int i = 0; i < 8; i++) {
        float inv = 1.0f / lrow[i];
        float o0, o1, o2, o3;
        unpack2(o[i][0], o0, o1);
        unpack2(o[i][1], o2, o3);
        float4 r4; r4.x = o0 * inv; r4.y = o1 * inv;
        r4.z = o2 * inv; r4.w = o3 * inv;
        *(float4*)&ctx[(size_t)(b * LL + q0 + (ty << 3) + i) * (HH * HDIM)
                       + h * HDIM + (tx << 2)] = r4;
    }
}

// ---------------------------------------------------------------------------
// kernel_launch
// ---------------------------------------------------------------------------
extern "C" void kernel_launch(void* const* d_in, const int* in_sizes, int n_in,
                              void* d_out, int out_size) {
    const float* x  = (const float*)d_in[0];
    const float* Wq = (const float*)d_in[1];
    const float* Wk = (const float*)d_in[2];
    const float* Wv = (const float*)d_in[3];
    const float* Wo = (const float*)d_in[4];
    float* out = (float*)d_out;

    float *pq, *pk, *pv, *pctx;
    cudaGetSymbolAddress((void**)&pq,   g_q);
    cudaGetSymbolAddress((void**)&pk,   g_k);
    cudaGetSymbolAddress((void**)&pv,   g_v);
    cudaGetSymbolAddress((void**)&pctx, g_ctx);

    const int smem_attn = (64 * 128 + 64 * 128 + 128 * 64 + 128 * 128)
                          * (int)sizeof(float);   // 163840
    cudaFuncSetAttribute(attn2,
                         cudaFuncAttributeMaxDynamicSharedMemorySize,
                         smem_attn);

    dim3 blk(256);

    // QKV projections (M=4096, K=1024)
    sgemm128<<<dim3(HH * HDIM / 128, BL / 128), blk>>>(x, Wq, pq, BL, HH * HDIM, DD);
    sgemm128<<<dim3(KVH * HDIM / 128, BL / 128), blk>>>(x, Wk, pk, BL, KVH * HDIM, DD);
    sgemm128<<<dim3(KVH * HDIM / 128, BL / 128), blk>>>(x, Wv, pv, BL, KVH * HDIM, DD);

    // RoPE
    {
        int total = BL * (HH + KVH) * 32;
        rope_kernel<<<(total + 255) / 256, blk>>>(pq, pk);
    }

    // attention
    attn2<<<dim3(LL / 128, HH, BB), blk, smem_attn>>>(pq, pk, pv, pctx);

    // output projection
    sgemm128<<<dim3(DD / 128, BL / 128), blk>>>(pctx, Wo, out, BL, DD, DD);
}

// round 4
// speedup vs baseline: 3.9506x; 1.3563x over previous
#include <cuda_runtime.h>
#include <cuda_bf16.h>
#include <math.h>
#include <stdint.h>

// Problem constants
#define BB   2
#define LL   2048
#define DD   1024
#define HH   16
#define KVH  4
#define HDIM 64
#define BL   (BB * LL)    // 4096

typedef unsigned long long ull;

// ---------------------------------------------------------------------------
// packed f32x2 helpers
// ---------------------------------------------------------------------------
__device__ __forceinline__ ull pack2(float x, float y) {
    ull r; asm("mov.b64 %0, {%1,%2};" : "=l"(r) : "f"(x), "f"(y)); return r;
}
__device__ __forceinline__ void unpack2(ull v, float& x, float& y) {
    asm("mov.b64 {%0,%1}, %2;" : "=f"(x), "=f"(y) : "l"(v));
}
__device__ __forceinline__ ull ffma2(ull a, ull b, ull c) {
    ull d; asm("fma.rn.f32x2 %0, %1, %2, %3;" : "=l"(d) : "l"(a), "l"(b), "l"(c));
    return d;
}
__device__ __forceinline__ ull fmul2(ull a, ull b) {
    ull d; asm("mul.rn.f32x2 %0, %1, %2;" : "=l"(d) : "l"(a), "l"(b));
    return d;
}

// ---------------------------------------------------------------------------
// mma.sync / ldmatrix / cp.async helpers (baseline PTX ISA — no 'a' features)
// ---------------------------------------------------------------------------
__device__ __forceinline__ uint32_t smem_u32(const void* p) {
    uint32_t a;
    asm("{ .reg .u64 t; cvta.to.shared.u64 t, %1; cvt.u32.u64 %0, t; }"
        : "=r"(a) : "l"(p));
    return a;
}
__device__ __forceinline__ void ldsm4(uint32_t addr, uint32_t* r) {
    asm volatile("ldmatrix.sync.aligned.m8n8.x4.shared.b16 {%0,%1,%2,%3}, [%4];"
                 : "=r"(r[0]), "=r"(r[1]), "=r"(r[2]), "=r"(r[3]) : "r"(addr));
}
__device__ __forceinline__ void mma16816(float* d, const uint32_t* a,
                                         const uint32_t* b) {
    asm volatile(
        "mma.sync.aligned.m16n8k16.row.col.f32.bf16.bf16.f32 "
        "{%0,%1,%2,%3}, {%4,%5,%6,%7}, {%8,%9}, {%0,%1,%2,%3};"
        : "+f"(d[0]), "+f"(d[1]), "+f"(d[2]), "+f"(d[3])
        : "r"(a[0]), "r"(a[1]), "r"(a[2]), "r"(a[3]), "r"(b[0]), "r"(b[1]));
}
__device__ __forceinline__ void cp16(uint32_t dst, const void* src) {
    asm volatile("cp.async.cg.shared.global [%0], [%1], 16;"
                 :: "r"(dst), "l"(src) : "memory");
}
#define CP_COMMIT() asm volatile("cp.async.commit_group;" ::: "memory")
#define CP_WAIT2()  asm volatile("cp.async.wait_group 2;" ::: "memory")

// ---------------------------------------------------------------------------
// Scratch (__device__ globals — no allocations allowed)
// ---------------------------------------------------------------------------
__device__ float g_q[BL * HH * HDIM];       // [4096][1024]
__device__ float g_kv[BL * 512];            // [4096][512]: cols 0..255 K, 256..511 V
__device__ float g_ctx[BL * HH * HDIM];

__device__ __nv_bfloat16 g_xhi[BL * DD];
__device__ __nv_bfloat16 g_xlo[BL * DD];
__device__ __nv_bfloat16 g_ctxhi[BL * DD];
__device__ __nv_bfloat16 g_ctxlo[BL * DD];
__device__ __nv_bfloat16 g_wqt_h[DD * DD];      // [N=1024][K=1024]
__device__ __nv_bfloat16 g_wqt_l[DD * DD];
__device__ __nv_bfloat16 g_wkvt_h[512 * DD];    // [N=512][K=1024]
__device__ __nv_bfloat16 g_wkvt_l[512 * DD];
__device__ __nv_bfloat16 g_wot_h[DD * DD];
__device__ __nv_bfloat16 g_wot_l[DD * DD];

// ---------------------------------------------------------------------------
// fp32 -> bf16 hi/lo split
// ---------------------------------------------------------------------------
__global__ __launch_bounds__(256)
void cvt_split(const float* __restrict__ in, __nv_bfloat16* __restrict__ hi,
               __nv_bfloat16* __restrict__ lo, int n4) {
    int i = blockIdx.x * 256 + threadIdx.x;
    if (i >= n4) return;
    float4 v = ((const float4*)in)[i];
    float vv[4] = {v.x, v.y, v.z, v.w};
    __nv_bfloat16 h[4], l[4];
#pragma unroll
    for (int j = 0; j < 4; j++) {
        h[j] = __float2bfloat16(vv[j]);
        l[j] = __float2bfloat16(vv[j] - __bfloat162float(h[j]));
    }
    ((uint64_t*)hi)[i] = *(uint64_t*)h;
    ((uint64_t*)lo)[i] = *(uint64_t*)l;
}

// ---------------------------------------------------------------------------
// W [K,N] fp32 -> W^T hi/lo bf16 [N,K]
// ---------------------------------------------------------------------------
__global__ __launch_bounds__(256)
void cvt_transpose(const float* __restrict__ W, __nv_bfloat16* __restrict__ hiT,
                   __nv_bfloat16* __restrict__ loT, int Kd, int Nd) {
    __shared__ float t[32][33];
    int n0 = blockIdx.x << 5, k0 = blockIdx.y << 5;
    int tx = threadIdx.x & 31, ty = threadIdx.x >> 5;   // 32 x 8
    for (int r = ty; r < 32; r += 8)
        t[r][tx] = W[(size_t)(k0 + r) * Nd + n0 + tx];
    __syncthreads();
    for (int r = ty; r < 32; r += 8) {
        float v = t[tx][r];
        __nv_bfloat16 h = __float2bfloat16(v);
        size_t o = (size_t)(n0 + r) * Kd + k0 + tx;
        hiT[o] = h;
        loT[o] = __float2bfloat16(v - __bfloat162float(h));
    }
}

// ---------------------------------------------------------------------------
// Tensor-core GEMM (mma.sync bf16x3): C[M,N] fp32 = A[M,K] @ BT[N,K]^T
// CTA 128x128, 8 warps (4M x 2N), BK=32, 3-stage cp.async pipeline.
// smem row stride 80B (conflict-free ldmatrix).
// ---------------------------------------------------------------------------
#define STG_BYTES 40960           // 4 subtiles * 128 rows * 80B
#define SUB_BYTES 10240

__global__ __launch_bounds__(256, 1)
void gemm_mma(const __nv_bfloat16* __restrict__ Ahi,
              const __nv_bfloat16* __restrict__ Alo,
              const __nv_bfloat16* __restrict__ Bhi,
              const __nv_bfloat16* __restrict__ Blo,
              float* __restrict__ C, int K, int ldc) {
    extern __shared__ char sm[];
    const uint32_t smb = smem_u32(sm);

    const int tid = threadIdx.x;
    const int lid = tid & 31;
    const int wid = tid >> 5;
    const int wm  = wid >> 1;          // 0..3
    const int wn  = wid & 1;           // 0..1
    const int row0 = blockIdx.y << 7;
    const int col0 = blockIdx.x << 7;
    const int NCH = K >> 5;            // chunks of 32

    // prefetch thread mapping: 8 x (s, r, u)
    const __nv_bfloat16* srcbase[4] = {Ahi, Alo, Bhi, Blo};

    auto prefetch = [&](int c, int stage) {
#pragma unroll
        for (int it = 0; it < 8; it++) {
            int i = tid + (it << 8);
            int s = i >> 9;
            int j = i & 511;
            int r = j >> 2;
            int u = j & 3;
            int grow = (s < 2 ? row0 : col0) + r;
            const __nv_bfloat16* src =
                srcbase[s] + (size_t)grow * K + (c << 5) + (u << 3);
            uint32_t dst = smb + stage * STG_BYTES + s * SUB_BYTES
                         + r * 80 + (u << 4);
            cp16(dst, src);
        }
    };

    prefetch(0, 0); CP_COMMIT();
    if (NCH > 1) prefetch(1, 1); CP_COMMIT();
    if (NCH > 2) prefetch(2, 2); CP_COMMIT();

    float acc[2][8][4];
#pragma unroll
    for (int a = 0; a < 2; a++)
#pragma unroll
        for (int b = 0; b < 8; b++)
#pragma unroll
            for (int d = 0; d < 4; d++) acc[a][b][d] = 0.0f;

    // per-thread ldmatrix base offsets (within a subtile)
    const uint32_t aoff = (uint32_t)((wm * 32 + (lid & 15)) * 80
                                     + ((lid >> 4) << 4));
    const uint32_t boff = (uint32_t)((wn * 64 + ((lid >> 4) << 3) + (lid & 7)) * 80
                                     + (((lid >> 3) & 1) << 4));

    for (int c = 0; c < NCH; c++) {
        CP_WAIT2();
        __syncthreads();

        const uint32_t sb = smb + (c % 3) * STG_BYTES;
        const uint32_t sa_h = sb;
        const uint32_t sa_l = sb + SUB_BYTES;
        const uint32_t sb_h = sb + 2 * SUB_BYTES;
        const uint32_t sb_l = sb + 3 * SUB_BYTES;

#pragma unroll
        for (int ks = 0; ks < 2; ks++) {
            uint32_t Ah[2][4], Al[2][4];
            ldsm4(sa_h + aoff + ks * 32, Ah[0]);
            ldsm4(sa_h + aoff + 16 * 80 + ks * 32, Ah[1]);
            ldsm4(sa_l + aoff + ks * 32, Al[0]);
            ldsm4(sa_l + aoff + 16 * 80 + ks * 32, Al[1]);
#pragma unroll
            for (int g = 0; g < 4; g++) {
                uint32_t Bh[4], Bl[4];
                ldsm4(sb_h + boff + g * (16 * 80) + ks * 32, Bh);
                ldsm4(sb_l + boff + g * (16 * 80) + ks * 32, Bl);
#pragma unroll
                for (int mi = 0; mi < 2; mi++) {
                    mma16816(acc[mi][2 * g],     Ah[mi], Bh);
                    mma16816(acc[mi][2 * g],     Ah[mi], Bl);
                    mma16816(acc[mi][2 * g],     Al[mi], Bh);
                    mma16816(acc[mi][2 * g + 1], Ah[mi], Bh + 2);
                    mma16816(acc[mi][2 * g + 1], Ah[mi], Bl + 2);
                    mma16816(acc[mi][2 * g + 1], Al[mi], Bh + 2);
                }
            }
        }
        __syncthreads();
        if (c + 3 < NCH) prefetch(c + 3, (c + 3) % 3);
        CP_COMMIT();
    }

    // epilogue
#pragma unroll
    for (int mi = 0; mi < 2; mi++) {
        int r0 = row0 + wm * 32 + mi * 16 + (lid >> 2);
#pragma unroll
        for (int ni = 0; ni < 8; ni++) {
            int cc = col0 + wn * 64 + ni * 8 + ((lid & 3) << 1);
            float2 v0; v0.x = acc[mi][ni][0]; v0.y = acc[mi][ni][1];
            float2 v1; v1.x = acc[mi][ni][2]; v1.y = acc[mi][ni][3];
            *(float2*)(C + (size_t)r0 * ldc + cc)       = v0;
            *(float2*)(C + (size_t)(r0 + 8) * ldc + cc) = v1;
        }
    }
}

// ---------------------------------------------------------------------------
// RoPE: q [4096][1024], kv [4096][512] (K in cols 0..255)
// ---------------------------------------------------------------------------
__global__ __launch_bounds__(256)
void rope_kernel(float* __restrict__ q, float* __restrict__ kv) {
    const int TQ = BL * HH * 32;
    const int TK = BL * KVH * 32;
    int idx = blockIdx.x * 256 + threadIdx.x;
    float* base;
    int j, pos;
    if (idx < TQ) {
        j = idx & 31;
        int t = idx >> 5;
        pos = (t >> 4) & (LL - 1);
        base = q + ((size_t)t << 6);
    } else if (idx < TQ + TK) {
        int id2 = idx - TQ;
        j = id2 & 31;
        int t = id2 >> 5;            // bl*4 + kvh
        int bl = t >> 2, kvh = t & 3;
        pos = bl & (LL - 1);
        base = kv + (size_t)bl * 512 + kvh * 64;
    } else return;
    float inv = powf(10000.0f, -(float)j * (1.0f / 32.0f));
    float ang = (float)pos * inv;
    float s, c;
    sincosf(ang, &s, &c);
    float x1 = base[j], x2 = base[j + 32];
    base[j]      = x1 * c - x2 * s;
    base[j + 32] = x2 * c + x1 * s;
}

// ---------------------------------------------------------------------------
// Flash attention (fp32 packed-FMA). K/V from fused g_kv [4096][512].
// ---------------------------------------------------------------------------
__global__ __launch_bounds__(256, 1)
void attn2(const float* __restrict__ Qg, const float* __restrict__ KVg,
           float* __restrict__ ctx) {
    extern __shared__ float smf[];
    float* Qs = smf;
    float* Ks = Qs + 64 * 128;
    float* Vs = Ks + 64 * 128;
    float* Ps = Vs + 128 * 64;

    const int tid = threadIdx.x;
    const int tx  = tid & 15;
    const int ty  = tid >> 4;
    const int q0  = blockIdx.x << 7;
    const int h   = blockIdx.y;
    const int b   = blockIdx.z;
    const int kvh = h >> 2;

    const float slope = exp2f(-0.5f * (float)(h + 1));
    const float scale = 0.125f;

    for (int i = tid; i < 2048; i += 256) {
        int r  = i >> 4;
        int d4 = (i & 15) << 2;
        float4 qv = *(const float4*)&Qg[
            (size_t)(b * LL + q0 + r) * (HH * HDIM) + h * HDIM + d4];
        int rs = r ^ (((d4 >> 2) & 3) << 3);
        Qs[(d4 + 0) * 128 + rs] = qv.x;
        Qs[(d4 + 1) * 128 + rs] = qv.y;
        Qs[(d4 + 2) * 128 + rs] = qv.z;
        Qs[(d4 + 3) * 128 + rs] = qv.w;
    }

    ull o[8][2];
    float mrow[8], lrow[8];
#pragma unroll
    for (int i = 0; i < 8; i++) {
        o[i][0] = 0ull; o[i][1] = 0ull;
        mrow[i] = -1e30f; lrow[i] = 0.0f;
    }

    for (int k0 = 0; k0 < LL; k0 += 128) {
        __syncthreads();
        for (int i = tid; i < 2048; i += 256) {
            int r  = i >> 4;
            int d4 = (i & 15) << 2;
            size_t g = (size_t)(b * LL + k0 + r) * 512 + kvh * 64 + d4;
            float4 kvv = *(const float4*)&KVg[g];
            float4 vv  = *(const float4*)&KVg[g + 256];
            int rs = r ^ (((d4 >> 2) & 3) << 3);
            Ks[(d4 + 0) * 128 + rs] = kvv.x;
            Ks[(d4 + 1) * 128 + rs] = kvv.y;
            Ks[(d4 + 2) * 128 + rs] = kvv.z;
            Ks[(d4 + 3) * 128 + rs] = kvv.w;
            *(float4*)&Vs[r * 64 + d4] = vv;
        }
        __syncthreads();

        ull s[8][4];
#pragma unroll
        for (int i = 0; i < 8; i++)
#pragma unroll
            for (int j = 0; j < 4; j++) s[i][j] = 0ull;

#pragma unroll 8
        for (int d = 0; d < 64; d++) {
            int sw = ((d >> 2) & 3) << 3;
            const float* qb = Qs + d * 128 + ((ty << 3) ^ sw);
            const float* kb = Ks + d * 128 + ((tx << 3) ^ sw);
            float4 ql = *(const float4*)qb;
            float4 qh = *(const float4*)(qb + 4);
            ulonglong2 kl = *(const ulonglong2*)kb;
            ulonglong2 kh = *(const ulonglong2*)(kb + 4);
            ull b0 = kl.x, b1 = kl.y, b2 = kh.x, b3 = kh.y;
            float qv[8] = {ql.x, ql.y, ql.z, ql.w, qh.x, qh.y, qh.z, qh.w};
#pragma unroll
            for (int i = 0; i < 8; i++) {
                ull ap = pack2(qv[i], qv[i]);
                s[i][0] = ffma2(ap, b0, s[i][0]);
                s[i][1] = ffma2(ap, b1, s[i][1]);
                s[i][2] = ffma2(ap, b2, s[i][2]);
                s[i][3] = ffma2(ap, b3, s[i][3]);
            }
        }

        const float cbase = (float)(k0 + (tx << 3));
#pragma unroll
        for (int i = 0; i < 8; i++) {
            float sf[8];
            unpack2(s[i][0], sf[0], sf[1]);
            unpack2(s[i][1], sf[2], sf[3]);
            unpack2(s[i][2], sf[4], sf[5]);
            unpack2(s[i][3], sf[6], sf[7]);
            float qpos = (float)(q0 + (ty << 3) + i);
            float bias0 = slope * (cbase - qpos);
#pragma unroll
            for (int j = 0; j < 8; j++)
                sf[j] = fmaf(sf[j], scale, bias0 + slope * (float)j);

            float mx = sf[0];
#pragma unroll
            for (int j = 1; j < 8; j++) mx = fmaxf(mx, sf[j]);
            mx = fmaxf(mx, __shfl_xor_sync(0xffffffffu, mx, 1));
            mx = fmaxf(mx, __shfl_xor_sync(0xffffffffu, mx, 2));
            mx = fmaxf(mx, __shfl_xor_sync(0xffffffffu, mx, 4));
            mx = fmaxf(mx, __shfl_xor_sync(0xffffffffu, mx, 8));

            float mn = fmaxf(mrow[i], mx);
            float c  = __expf(mrow[i] - mn);
            mrow[i]  = mn;

            float p[8], ps = 0.0f;
#pragma unroll
            for (int j = 0; j < 8; j++) {
                p[j] = __expf(sf[j] - mn);
                ps += p[j];
            }
            ps += __shfl_xor_sync(0xffffffffu, ps, 1);
            ps += __shfl_xor_sync(0xffffffffu, ps, 2);
            ps += __shfl_xor_sync(0xffffffffu, ps, 4);
            ps += __shfl_xor_sync(0xffffffffu, ps, 8);
            lrow[i] = lrow[i] * c + ps;

            ull cp = pack2(c, c);
            o[i][0] = fmul2(o[i][0], cp);
            o[i][1] = fmul2(o[i][1], cp);

            float* pd = Ps + ((ty << 3) + i) * 128 + (tx << 3);
            float4 p0; p0.x = p[0]; p0.y = p[1]; p0.z = p[2]; p0.w = p[3];
            float4 p1; p1.x = p[4]; p1.y = p[5]; p1.z = p[6]; p1.w = p[7];
            *(float4*)pd       = p0;
            *(float4*)(pd + 4) = p1;
        }
        __syncthreads();

#pragma unroll 4
        for (int kc = 0; kc < 128; kc++) {
            ulonglong2 vv = *(const ulonglong2*)&Vs[kc * 64 + (tx << 2)];
            const float* pc = Ps + (ty << 3) * 128 + kc;
#pragma unroll
            for (int i = 0; i < 8; i++) {
                float pvv = pc[i * 128];
                ull pp = pack2(pvv, pvv);
                o[i][0] = ffma2(pp, vv.x, o[i][0]);
                o[i][1] = ffma2(pp, vv.y, o[i][1]);
            }
        }
    }

#pragma unroll
    for (int i = 0; i < 8; i++) {
        float inv = 1.0f / lrow[i];
        float o0, o1, o2, o3;
        unpack2(o[i][0], o0, o1);
        unpack2(o[i][1], o2, o3);
        float4 r4; r4.x = o0 * inv; r4.y = o1 * inv;
        r4.z = o2 * inv; r4.w = o3 * inv;
        *(float4*)&ctx[(size_t)(b * LL + q0 + (ty << 3) + i) * (HH * HDIM)
                       + h * HDIM + (tx << 2)] = r4;
    }
}

// ---------------------------------------------------------------------------
// kernel_launch
// ---------------------------------------------------------------------------
extern "C" void kernel_launch(void* const* d_in, const int* in_sizes, int n_in,
                              void* d_out, int out_size) {
    const float* x  = (const float*)d_in[0];
    const float* Wq = (const float*)d_in[1];
    const float* Wk = (const float*)d_in[2];
    const float* Wv = (const float*)d_in[3];
    const float* Wo = (const float*)d_in[4];
    float* out = (float*)d_out;

    float *pq, *pkv, *pctx;
    cudaGetSymbolAddress((void**)&pq,   g_q);
    cudaGetSymbolAddress((void**)&pkv,  g_kv);
    cudaGetSymbolAddress((void**)&pctx, g_ctx);

    __nv_bfloat16 *xhi, *xlo, *cthi, *ctlo;
    __nv_bfloat16 *wqh, *wql, *wkvh, *wkvl, *woh, *wol;
    cudaGetSymbolAddress((void**)&xhi,  g_xhi);
    cudaGetSymbolAddress((void**)&xlo,  g_xlo);
    cudaGetSymbolAddress((void**)&cthi, g_ctxhi);
    cudaGetSymbolAddress((void**)&ctlo, g_ctxlo);
    cudaGetSymbolAddress((void**)&wqh,  g_wqt_h);
    cudaGetSymbolAddress((void**)&wql,  g_wqt_l);
    cudaGetSymbolAddress((void**)&wkvh, g_wkvt_h);
    cudaGetSymbolAddress((void**)&wkvl, g_wkvt_l);
    cudaGetSymbolAddress((void**)&woh,  g_wot_h);
    cudaGetSymbolAddress((void**)&wol,  g_wot_l);

    const int smem_gemm = 3 * STG_BYTES;   // 122880
    cudaFuncSetAttribute(gemm_mma, cudaFuncAttributeMaxDynamicSharedMemorySize,
                         smem_gemm);
    const int smem_attn = (64 * 128 + 64 * 128 + 128 * 64 + 128 * 128)
                          * (int)sizeof(float);
    cudaFuncSetAttribute(attn2, cudaFuncAttributeMaxDynamicSharedMemorySize,
                         smem_attn);

    dim3 blk(256);

    // conversions: x split, weights transposed+split (K into kv rows 0..255,
    // V into rows 256..511)
    cvt_split<<<(BL * DD / 4 + 255) / 256, blk>>>(x, xhi, xlo, BL * DD / 4);
    cvt_transpose<<<dim3(DD / 32, DD / 32), blk>>>(Wq, wqh, wql, DD, DD);
    cvt_transpose<<<dim3(256 / 32, DD / 32), blk>>>(Wk, wkvh, wkvl, DD, 256);
    cvt_transpose<<<dim3(256 / 32, DD / 32), blk>>>(
        Wv, wkvh + 256 * DD, wkvl + 256 * DD, DD, 256);
    cvt_transpose<<<dim3(DD / 32, DD / 32), blk>>>(Wo, woh, wol, DD, DD);

    // projections on tensor cores (mma.sync bf16x3)
    gemm_mma<<<dim3(DD / 128, BL / 128), blk, smem_gemm>>>(
        xhi, xlo, wqh, wql, pq, DD, DD);
    gemm_mma<<<dim3(512 / 128, BL / 128), blk, smem_gemm>>>(
        xhi, xlo, wkvh, wkvl, pkv, DD, 512);

    // RoPE
    {
        int total = BL * (HH + KVH) * 32;
        rope_kernel<<<(total + 255) / 256, blk>>>(pq, pkv);
    }

    // attention (fp32)
    attn2<<<dim3(LL / 128, HH, BB), blk, smem_attn>>>(pq, pkv, pctx);

    // output projection
    cvt_split<<<(BL * DD / 4 + 255) / 256, blk>>>(pctx, cthi, ctlo, BL * DD / 4);
    gemm_mma<<<dim3(DD / 128, BL / 128), blk, smem_gemm>>>(
        cthi, ctlo, woh, wol, out, DD, DD);
}

// round 5
// speedup vs baseline: 7.6398x; 1.9338x over previous
#include <cuda_runtime.h>
#include <cuda_bf16.h>
#include <math.h>
#include <stdint.h>

// Problem constants
#define BB   2
#define LL   2048
#define DD   1024
#define HH   16
#define KVH  4
#define HDIM 64
#define BL   (BB * LL)    // 4096

typedef unsigned long long ull;

// ---------------------------------------------------------------------------
// mma.sync / ldmatrix / cp.async helpers (baseline PTX ISA)
// ---------------------------------------------------------------------------
__device__ __forceinline__ uint32_t smem_u32(const void* p) {
    uint32_t a;
    asm("{ .reg .u64 t; cvta.to.shared.u64 t, %1; cvt.u32.u64 %0, t; }"
        : "=r"(a) : "l"(p));
    return a;
}
__device__ __forceinline__ void ldsm4(uint32_t addr, uint32_t* r) {
    asm volatile("ldmatrix.sync.aligned.m8n8.x4.shared.b16 {%0,%1,%2,%3}, [%4];"
                 : "=r"(r[0]), "=r"(r[1]), "=r"(r[2]), "=r"(r[3]) : "r"(addr));
}
__device__ __forceinline__ void ldsm4t(uint32_t addr, uint32_t* r) {
    asm volatile("ldmatrix.sync.aligned.m8n8.x4.trans.shared.b16 {%0,%1,%2,%3}, [%4];"
                 : "=r"(r[0]), "=r"(r[1]), "=r"(r[2]), "=r"(r[3]) : "r"(addr));
}
__device__ __forceinline__ void mma16816(float* d, const uint32_t* a,
                                         const uint32_t* b) {
    asm volatile(
        "mma.sync.aligned.m16n8k16.row.col.f32.bf16.bf16.f32 "
        "{%0,%1,%2,%3}, {%4,%5,%6,%7}, {%8,%9}, {%0,%1,%2,%3};"
        : "+f"(d[0]), "+f"(d[1]), "+f"(d[2]), "+f"(d[3])
        : "r"(a[0]), "r"(a[1]), "r"(a[2]), "r"(a[3]), "r"(b[0]), "r"(b[1]));
}
__device__ __forceinline__ void cp16(uint32_t dst, const void* src) {
    asm volatile("cp.async.cg.shared.global [%0], [%1], 16;"
                 :: "r"(dst), "l"(src) : "memory");
}
#define CP_COMMIT() asm volatile("cp.async.commit_group;" ::: "memory")
#define CP_WAIT2()  asm volatile("cp.async.wait_group 2;" ::: "memory")
#define CP_WAIT1()  asm volatile("cp.async.wait_group 1;" ::: "memory")

__device__ __forceinline__ uint32_t packbf(float lo, float hi) {
    __nv_bfloat162 t = __floats2bfloat162_rn(lo, hi);
    return *(uint32_t*)&t;
}
__device__ __forceinline__ float bfhi(float v) {
    return __bfloat162float(__float2bfloat16(v));
}

// ---------------------------------------------------------------------------
// Scratch (__device__ globals — no allocations allowed)
// ---------------------------------------------------------------------------
__device__ float g_q[BL * HH * HDIM];       // [4096][1024] fp32
__device__ float g_kv[BL * 512];            // [4096][512] fp32 (K|V)
__device__ float g_ctx[BL * HH * HDIM];

__device__ __nv_bfloat16 g_xhi[BL * DD];
__device__ __nv_bfloat16 g_xlo[BL * DD];
__device__ __nv_bfloat16 g_ctxhi[BL * DD];
__device__ __nv_bfloat16 g_ctxlo[BL * DD];
__device__ __nv_bfloat16 g_wqt_h[DD * DD];
__device__ __nv_bfloat16 g_wqt_l[DD * DD];
__device__ __nv_bfloat16 g_wkvt_h[512 * DD];
__device__ __nv_bfloat16 g_wkvt_l[512 * DD];
__device__ __nv_bfloat16 g_wot_h[DD * DD];
__device__ __nv_bfloat16 g_wot_l[DD * DD];

// roped + split Q/K/V for tensor-core attention
__device__ __nv_bfloat16 g_qh[BL * DD];     // [4096][1024]
__device__ __nv_bfloat16 g_ql[BL * DD];
__device__ __nv_bfloat16 g_kh[BL * 256];    // [4096][256]
__device__ __nv_bfloat16 g_kl[BL * 256];
__device__ __nv_bfloat16 g_vh[BL * 256];
__device__ __nv_bfloat16 g_vl[BL * 256];

// ---------------------------------------------------------------------------
// fp32 -> bf16 hi/lo split
// ---------------------------------------------------------------------------
__global__ __launch_bounds__(256)
void cvt_split(const float* __restrict__ in, __nv_bfloat16* __restrict__ hi,
               __nv_bfloat16* __restrict__ lo, int n4) {
    int i = blockIdx.x * 256 + threadIdx.x;
    if (i >= n4) return;
    float4 v = ((const float4*)in)[i];
    float vv[4] = {v.x, v.y, v.z, v.w};
    __nv_bfloat16 h[4], l[4];
#pragma unroll
    for (int j = 0; j < 4; j++) {
        h[j] = __float2bfloat16(vv[j]);
        l[j] = __float2bfloat16(vv[j] - __bfloat162float(h[j]));
    }
    ((uint64_t*)hi)[i] = *(uint64_t*)h;
    ((uint64_t*)lo)[i] = *(uint64_t*)l;
}

// ---------------------------------------------------------------------------
// W [K,N] fp32 -> W^T hi/lo bf16 [N,K]
// ---------------------------------------------------------------------------
__global__ __launch_bounds__(256)
void cvt_transpose(const float* __restrict__ W, __nv_bfloat16* __restrict__ hiT,
                   __nv_bfloat16* __restrict__ loT, int Kd, int Nd) {
    __shared__ float t[32][33];
    int n0 = blockIdx.x << 5, k0 = blockIdx.y << 5;
    int tx = threadIdx.x & 31, ty = threadIdx.x >> 5;
    for (int r = ty; r < 32; r += 8)
        t[r][tx] = W[(size_t)(k0 + r) * Nd + n0 + tx];
    __syncthreads();
    for (int r = ty; r < 32; r += 8) {
        float v = t[tx][r];
        __nv_bfloat16 h = __float2bfloat16(v);
        size_t o = (size_t)(n0 + r) * Kd + k0 + tx;
        hiT[o] = h;
        loT[o] = __float2bfloat16(v - __bfloat162float(h));
    }
}

// ---------------------------------------------------------------------------
// Tensor-core GEMM (mma.sync bf16x3), unchanged from round 4.
// ---------------------------------------------------------------------------
#define STG_BYTES 40960
#define SUB_BYTES 10240

__global__ __launch_bounds__(256, 1)
void gemm_mma(const __nv_bfloat16* __restrict__ Ahi,
              const __nv_bfloat16* __restrict__ Alo,
              const __nv_bfloat16* __restrict__ Bhi,
              const __nv_bfloat16* __restrict__ Blo,
              float* __restrict__ C, int K, int ldc) {
    extern __shared__ char sm[];
    const uint32_t smb = smem_u32(sm);

    const int tid = threadIdx.x;
    const int lid = tid & 31;
    const int wid = tid >> 5;
    const int wm  = wid >> 1;
    const int wn  = wid & 1;
    const int row0 = blockIdx.y << 7;
    const int col0 = blockIdx.x << 7;
    const int NCH = K >> 5;

    const __nv_bfloat16* srcbase[4] = {Ahi, Alo, Bhi, Blo};

    auto prefetch = [&](int c, int stage) {
#pragma unroll
        for (int it = 0; it < 8; it++) {
            int i = tid + (it << 8);
            int s = i >> 9;
            int j = i & 511;
            int r = j >> 2;
            int u = j & 3;
            int grow = (s < 2 ? row0 : col0) + r;
            const __nv_bfloat16* src =
                srcbase[s] + (size_t)grow * K + (c << 5) + (u << 3);
            uint32_t dst = smb + stage * STG_BYTES + s * SUB_BYTES
                         + r * 80 + (u << 4);
            cp16(dst, src);
        }
    };

    prefetch(0, 0); CP_COMMIT();
    if (NCH > 1) prefetch(1, 1); CP_COMMIT();
    if (NCH > 2) prefetch(2, 2); CP_COMMIT();

    float acc[2][8][4];
#pragma unroll
    for (int a = 0; a < 2; a++)
#pragma unroll
        for (int b = 0; b < 8; b++)
#pragma unroll
            for (int d = 0; d < 4; d++) acc[a][b][d] = 0.0f;

    const uint32_t aoff = (uint32_t)((wm * 32 + (lid & 15)) * 80
                                     + ((lid >> 4) << 4));
    const uint32_t boff = (uint32_t)((wn * 64 + ((lid >> 4) << 3) + (lid & 7)) * 80
                                     + (((lid >> 3) & 1) << 4));

    for (int c = 0; c < NCH; c++) {
        CP_WAIT2();
        __syncthreads();

        const uint32_t sb = smb + (c % 3) * STG_BYTES;
        const uint32_t sa_h = sb;
        const uint32_t sa_l = sb + SUB_BYTES;
        const uint32_t sb_h = sb + 2 * SUB_BYTES;
        const uint32_t sb_l = sb + 3 * SUB_BYTES;

#pragma unroll
        for (int ks = 0; ks < 2; ks++) {
            uint32_t Ah[2][4], Al[2][4];
            ldsm4(sa_h + aoff + ks * 32, Ah[0]);
            ldsm4(sa_h + aoff + 16 * 80 + ks * 32, Ah[1]);
            ldsm4(sa_l + aoff + ks * 32, Al[0]);
            ldsm4(sa_l + aoff + 16 * 80 + ks * 32, Al[1]);
#pragma unroll
            for (int g = 0; g < 4; g++) {
                uint32_t Bh[4], Bl[4];
                ldsm4(sb_h + boff + g * (16 * 80) + ks * 32, Bh);
                ldsm4(sb_l + boff + g * (16 * 80) + ks * 32, Bl);
#pragma unroll
                for (int mi = 0; mi < 2; mi++) {
                    mma16816(acc[mi][2 * g],     Ah[mi], Bh);
                    mma16816(acc[mi][2 * g],     Ah[mi], Bl);
                    mma16816(acc[mi][2 * g],     Al[mi], Bh);
                    mma16816(acc[mi][2 * g + 1], Ah[mi], Bh + 2);
                    mma16816(acc[mi][2 * g + 1], Ah[mi], Bl + 2);
                    mma16816(acc[mi][2 * g + 1], Al[mi], Bh + 2);
                }
            }
        }
        __syncthreads();
        if (c + 3 < NCH) prefetch(c + 3, (c + 3) % 3);
        CP_COMMIT();
    }

#pragma unroll
    for (int mi = 0; mi < 2; mi++) {
        int r0 = row0 + wm * 32 + mi * 16 + (lid >> 2);
#pragma unroll
        for (int ni = 0; ni < 8; ni++) {
            int cc = col0 + wn * 64 + ni * 8 + ((lid & 3) << 1);
            float2 v0; v0.x = acc[mi][ni][0]; v0.y = acc[mi][ni][1];
            float2 v1; v1.x = acc[mi][ni][2]; v1.y = acc[mi][ni][3];
            *(float2*)(C + (size_t)r0 * ldc + cc)       = v0;
            *(float2*)(C + (size_t)(r0 + 8) * ldc + cc) = v1;
        }
    }
}

// ---------------------------------------------------------------------------
// RoPE + hi/lo split: q fp32 [4096][1024], kv fp32 [4096][512] ->
//   qh/ql [4096][1024], kh/kl/vh/vl [4096][256]  (bf16)
// ---------------------------------------------------------------------------
__global__ __launch_bounds__(256)
void rope_split(const float* __restrict__ q, const float* __restrict__ kv,
                __nv_bfloat16* __restrict__ qh, __nv_bfloat16* __restrict__ ql,
                __nv_bfloat16* __restrict__ kh, __nv_bfloat16* __restrict__ kl,
                __nv_bfloat16* __restrict__ vh, __nv_bfloat16* __restrict__ vl) {
    const int TQ = BL * HH * 32;
    const int TK = BL * KVH * 32;
    const int TV = BL * KVH * 32;
    int idx = blockIdx.x * 256 + threadIdx.x;
    if (idx < TQ + TK) {
        // roped halves
        const float* base;
        size_t o;
        __nv_bfloat16 *dh, *dl;
        int j, pos;
        if (idx < TQ) {
            j = idx & 31;
            int t = idx >> 5;          // token*16 + h
            int token = t >> 4, h = t & 15;
            pos = token & (LL - 1);
            base = q + ((size_t)t << 6);
            o = (size_t)token * 1024 + h * 64 + j;
            dh = qh; dl = ql;
        } else {
            int id2 = idx - TQ;
            j = id2 & 31;
            int t = id2 >> 5;          // token*4 + kvh
            int token = t >> 2, kvh2 = t & 3;
            pos = token & (LL - 1);
            base = kv + (size_t)token * 512 + kvh2 * 64;
            o = (size_t)token * 256 + kvh2 * 64 + j;
            dh = kh; dl = kl;
        }
        float inv = powf(10000.0f, -(float)j * (1.0f / 32.0f));
        float ang = (float)pos * inv;
        float s, c;
        sincosf(ang, &s, &c);
        float x1 = base[j], x2 = base[j + 32];
        float y1 = x1 * c - x2 * s;
        float y2 = x2 * c + x1 * s;
        __nv_bfloat16 h1 = __float2bfloat16(y1);
        __nv_bfloat16 h2 = __float2bfloat16(y2);
        dh[o]      = h1;
        dh[o + 32] = h2;
        dl[o]      = __float2bfloat16(y1 - __bfloat162float(h1));
        dl[o + 32] = __float2bfloat16(y2 - __bfloat162float(h2));
    } else if (idx < TQ + TK + TV) {
        int id2 = idx - TQ - TK;
        int j = id2 & 31;
        int t = id2 >> 5;
        int token = t >> 2, kvh2 = t & 3;
        const float* base = kv + (size_t)token * 512 + 256 + kvh2 * 64;
        size_t o = (size_t)token * 256 + kvh2 * 64 + j;
        float x1 = base[j], x2 = base[j + 32];
        __nv_bfloat16 h1 = __float2bfloat16(x1);
        __nv_bfloat16 h2 = __float2bfloat16(x2);
        vh[o]      = h1;
        vh[o + 32] = h2;
        vl[o]      = __float2bfloat16(x1 - __bfloat162float(h1));
        vl[o + 32] = __float2bfloat16(x2 - __bfloat162float(h2));
    }
}

// ---------------------------------------------------------------------------
// Tensor-core flash attention (bf16x3 QK and PV).
// grid (16, 16, 2), 256 thr (8 warps x 16 q-rows). KV tiles of 64 keys,
// 2-stage cp.async pipeline. smem rows stride 144B (conflict-free ldmatrix).
// ---------------------------------------------------------------------------
#define AST 144                    // row stride bytes
#define QSUB (128 * AST)           // 18432
#define KVSUB (64 * AST)           // 9216
#define KVSTG (4 * KVSUB)          // 36864: kh,kl,vh,vl
#define ATT_SMEM (2 * QSUB + 2 * KVSTG)   // 110592

__global__ __launch_bounds__(256, 1)
void attn_mma(const __nv_bfloat16* __restrict__ qh, const __nv_bfloat16* __restrict__ ql,
              const __nv_bfloat16* __restrict__ kh, const __nv_bfloat16* __restrict__ kl,
              const __nv_bfloat16* __restrict__ vh, const __nv_bfloat16* __restrict__ vl,
              float* __restrict__ ctx) {
    extern __shared__ char sm[];
    const uint32_t smb  = smem_u32(sm);
    const uint32_t Qh_s = smb;
    const uint32_t Ql_s = smb + QSUB;
    const uint32_t KV_s = smb + 2 * QSUB;

    const int tid = threadIdx.x;
    const int lid = tid & 31;
    const int wid = tid >> 5;
    const int q0  = blockIdx.x << 7;
    const int h   = blockIdx.y;
    const int b   = blockIdx.z;
    const int kvh2 = h >> 2;

    const float slope = exp2f(-0.5f * (float)(h + 1));
    const float scale = 0.125f;

    // --- Q tile cp.async (group 0, together with KV tile 0) ---
#pragma unroll
    for (int t = 0; t < 8; t++) {
        int i = tid + (t << 8);
        int s = i >> 10;               // 0: qh, 1: ql
        int j = i & 1023;
        int r = j >> 3;
        int u = j & 7;
        const __nv_bfloat16* src =
            (s ? ql : qh) + (size_t)(b * LL + q0 + r) * 1024 + h * 64 + (u << 3);
        cp16(smb + s * QSUB + r * AST + (u << 4), src);
    }

    const __nv_bfloat16* kvsrc[4] = {kh, kl, vh, vl};
    auto pf = [&](int c, int st) {
#pragma unroll
        for (int t = 0; t < 8; t++) {
            int i = tid + (t << 8);
            int s = i >> 9;
            int j = i & 511;
            int r = j >> 3;
            int u = j & 7;
            const __nv_bfloat16* src =
                kvsrc[s] + (size_t)(b * LL + (c << 6) + r) * 256 + kvh2 * 64 + (u << 3);
            cp16(KV_s + st * KVSTG + s * KVSUB + r * AST + (u << 4), src);
        }
    };

    pf(0, 0); CP_COMMIT();
    pf(1, 1); CP_COMMIT();

    // A-frag ldmatrix address for Q (per warp)
    const uint32_t qaddr = (uint32_t)((wid * 16 + (lid & 15)) * AST
                                      + ((lid >> 4) << 4));
    // B-frag (non-trans) base for K: per 16-key group g, k16 step ks:
    //   (g*16 + (lid>>4)*8 + (lid&7))*AST + ((lid>>3)&1)*16 + ks*32
    const uint32_t kaddr = (uint32_t)((((lid >> 4) << 3) + (lid & 7)) * AST
                                      + (((lid >> 3) & 1) << 4));
    // B-frag (trans) base for V: (kt*16 + (lid&15))*AST + (dg*16 + (lid>>4)*8)*2
    const uint32_t vaddr = (uint32_t)((lid & 15) * AST + ((lid >> 4) << 4));

    uint32_t AQh[4][4], AQl[4][4];
    float o[8][4];
#pragma unroll
    for (int i = 0; i < 8; i++)
#pragma unroll
        for (int e = 0; e < 4; e++) o[i][e] = 0.0f;
    float m0 = -1e30f, m1 = -1e30f, lsum0 = 0.0f, lsum1 = 0.0f;
    const float qrow0 = (float)(q0 + wid * 16 + (lid >> 2));
    const float qrow1 = qrow0 + 8.0f;

    const int NTILES = LL / 64;   // 32

    for (int c = 0; c < NTILES; c++) {
        CP_WAIT1();
        __syncthreads();

        if (c == 0) {
#pragma unroll
            for (int kt = 0; kt < 4; kt++) {
                ldsm4(Qh_s + qaddr + kt * 32, AQh[kt]);
                ldsm4(Ql_s + qaddr + kt * 32, AQl[kt]);
            }
        }

        const uint32_t sb  = KV_s + (c & 1) * KVSTG;
        const uint32_t skh = sb;
        const uint32_t skl = sb + KVSUB;
        const uint32_t svh = sb + 2 * KVSUB;
        const uint32_t svl = sb + 3 * KVSUB;

        // ---- S = Q.K^T (bf16x3), 64 keys = 8 n8-tiles ----
        float S[8][4];
#pragma unroll
        for (int i = 0; i < 8; i++)
#pragma unroll
            for (int e = 0; e < 4; e++) S[i][e] = 0.0f;

#pragma unroll
        for (int g = 0; g < 4; g++) {
#pragma unroll
            for (int ks = 0; ks < 4; ks++) {
                uint32_t Bh[4], Bl[4];
                uint32_t base = (g << 4) * AST + kaddr + (ks << 5);
                ldsm4(skh + base, Bh);
                ldsm4(skl + base, Bl);
                mma16816(S[2 * g],     AQh[ks], Bh);
                mma16816(S[2 * g],     AQh[ks], Bl);
                mma16816(S[2 * g],     AQl[ks], Bh);
                mma16816(S[2 * g + 1], AQh[ks], Bh + 2);
                mma16816(S[2 * g + 1], AQh[ks], Bl + 2);
                mma16816(S[2 * g + 1], AQl[ks], Bh + 2);
            }
        }

        // ---- softmax (online), scores for 64 keys ----
        const float colb = (float)((c << 6) + 2 * (lid & 3));
        const float sb0 = slope * (colb - qrow0);
        const float sb1 = slope * (colb - qrow1);
        float mx0 = -1e30f, mx1 = -1e30f;
#pragma unroll
        for (int nt = 0; nt < 8; nt++) {
            float bo = slope * (float)(nt << 3);
            S[nt][0] = fmaf(S[nt][0], scale, sb0 + bo);
            S[nt][1] = fmaf(S[nt][1], scale, sb0 + bo + slope);
            S[nt][2] = fmaf(S[nt][2], scale, sb1 + bo);
            S[nt][3] = fmaf(S[nt][3], scale, sb1 + bo + slope);
            mx0 = fmaxf(mx0, fmaxf(S[nt][0], S[nt][1]));
            mx1 = fmaxf(mx1, fmaxf(S[nt][2], S[nt][3]));
        }
        mx0 = fmaxf(mx0, __shfl_xor_sync(0xffffffffu, mx0, 1));
        mx0 = fmaxf(mx0, __shfl_xor_sync(0xffffffffu, mx0, 2));
        mx1 = fmaxf(mx1, __shfl_xor_sync(0xffffffffu, mx1, 1));
        mx1 = fmaxf(mx1, __shfl_xor_sync(0xffffffffu, mx1, 2));

        float mn0 = fmaxf(m0, mx0);
        float mn1 = fmaxf(m1, mx1);
        float corr0 = __expf(m0 - mn0);
        float corr1 = __expf(m1 - mn1);
        m0 = mn0; m1 = mn1;

        float ps0 = 0.0f, ps1 = 0.0f;
#pragma unroll
        for (int nt = 0; nt < 8; nt++) {
            S[nt][0] = __expf(S[nt][0] - m0);
            S[nt][1] = __expf(S[nt][1] - m0);
            S[nt][2] = __expf(S[nt][2] - m1);
            S[nt][3] = __expf(S[nt][3] - m1);
            ps0 += S[nt][0] + S[nt][1];
            ps1 += S[nt][2] + S[nt][3];
        }
        ps0 += __shfl_xor_sync(0xffffffffu, ps0, 1);
        ps0 += __shfl_xor_sync(0xffffffffu, ps0, 2);
        ps1 += __shfl_xor_sync(0xffffffffu, ps1, 1);
        ps1 += __shfl_xor_sync(0xffffffffu, ps1, 2);
        lsum0 = lsum0 * corr0 + ps0;
        lsum1 = lsum1 * corr1 + ps1;

#pragma unroll
        for (int nt = 0; nt < 8; nt++) {
            o[nt][0] *= corr0;
            o[nt][1] *= corr0;
            o[nt][2] *= corr1;
            o[nt][3] *= corr1;
        }

        // ---- P -> A-fragments (hi/lo) in registers ----
        uint32_t PAh[4][4], PAl[4][4];
#pragma unroll
        for (int kt = 0; kt < 4; kt++) {
            float p00 = S[2 * kt][0],     p01 = S[2 * kt][1];
            float p02 = S[2 * kt][2],     p03 = S[2 * kt][3];
            float p10 = S[2 * kt + 1][0], p11 = S[2 * kt + 1][1];
            float p12 = S[2 * kt + 1][2], p13 = S[2 * kt + 1][3];
            float h00 = bfhi(p00), h01 = bfhi(p01), h02 = bfhi(p02), h03 = bfhi(p03);
            float h10 = bfhi(p10), h11 = bfhi(p11), h12 = bfhi(p12), h13 = bfhi(p13);
            PAh[kt][0] = packbf(h00, h01);
            PAh[kt][1] = packbf(h02, h03);
            PAh[kt][2] = packbf(h10, h11);
            PAh[kt][3] = packbf(h12, h13);
            PAl[kt][0] = packbf(p00 - h00, p01 - h01);
            PAl[kt][1] = packbf(p02 - h02, p03 - h03);
            PAl[kt][2] = packbf(p10 - h10, p11 - h11);
            PAl[kt][3] = packbf(p12 - h12, p13 - h13);
        }

        // ---- O += P @ V (bf16x3), V via ldmatrix.trans ----
#pragma unroll
        for (int dg = 0; dg < 4; dg++) {
#pragma unroll
            for (int kt = 0; kt < 4; kt++) {
                uint32_t Bvh[4], Bvl[4];
                uint32_t base = (kt << 4) * AST + vaddr + (dg << 5);
                ldsm4t(svh + base, Bvh);
                ldsm4t(svl + base, Bvl);
                mma16816(o[2 * dg],     PAh[kt], Bvh);
                mma16816(o[2 * dg],     PAh[kt], Bvl);
                mma16816(o[2 * dg],     PAl[kt], Bvh);
                mma16816(o[2 * dg + 1], PAh[kt], Bvh + 2);
                mma16816(o[2 * dg + 1], PAh[kt], Bvl + 2);
                mma16816(o[2 * dg + 1], PAl[kt], Bvh + 2);
            }
        }

        __syncthreads();
        if (c + 2 < NTILES) pf(c + 2, c & 1);
        CP_COMMIT();
    }

    // ---- epilogue ----
    float inv0 = 1.0f / lsum0;
    float inv1 = 1.0f / lsum1;
    const int r0 = b * LL + q0 + wid * 16 + (lid >> 2);
#pragma unroll
    for (int nt = 0; nt < 8; nt++) {
        int cc = h * 64 + nt * 8 + ((lid & 3) << 1);
        float2 v0; v0.x = o[nt][0] * inv0; v0.y = o[nt][1] * inv0;
        float2 v1; v1.x = o[nt][2] * inv1; v1.y = o[nt][3] * inv1;
        *(float2*)(ctx + (size_t)r0 * 1024 + cc)       = v0;
        *(float2*)(ctx + (size_t)(r0 + 8) * 1024 + cc) = v1;
    }
}

// ---------------------------------------------------------------------------
// kernel_launch
// ---------------------------------------------------------------------------
extern "C" void kernel_launch(void* const* d_in, const int* in_sizes, int n_in,
                              void* d_out, int out_size) {
    const float* x  = (const float*)d_in[0];
    const float* Wq = (const float*)d_in[1];
    const float* Wk = (const float*)d_in[2];
    const float* Wv = (const float*)d_in[3];
    const float* Wo = (const float*)d_in[4];
    float* out = (float*)d_out;

    float *pq, *pkv, *pctx;
    cudaGetSymbolAddress((void**)&pq,   g_q);
    cudaGetSymbolAddress((void**)&pkv,  g_kv);
    cudaGetSymbolAddress((void**)&pctx, g_ctx);

    __nv_bfloat16 *xhi, *xlo, *cthi, *ctlo;
    __nv_bfloat16 *wqh, *wql, *wkvh, *wkvl, *woh, *wol;
    __nv_bfloat16 *aqh, *aql, *akh, *akl, *avh, *avl;
    cudaGetSymbolAddress((void**)&xhi,  g_xhi);
    cudaGetSymbolAddress((void**)&xlo,  g_xlo);
    cudaGetSymbolAddress((void**)&cthi, g_ctxhi);
    cudaGetSymbolAddress((void**)&ctlo, g_ctxlo);
    cudaGetSymbolAddress((void**)&wqh,  g_wqt_h);
    cudaGetSymbolAddress((void**)&wql,  g_wqt_l);
    cudaGetSymbolAddress((void**)&wkvh, g_wkvt_h);
    cudaGetSymbolAddress((void**)&wkvl, g_wkvt_l);
    cudaGetSymbolAddress((void**)&woh,  g_wot_h);
    cudaGetSymbolAddress((void**)&wol,  g_wot_l);
    cudaGetSymbolAddress((void**)&aqh,  g_qh);
    cudaGetSymbolAddress((void**)&aql,  g_ql);
    cudaGetSymbolAddress((void**)&akh,  g_kh);
    cudaGetSymbolAddress((void**)&akl,  g_kl);
    cudaGetSymbolAddress((void**)&avh,  g_vh);
    cudaGetSymbolAddress((void**)&avl,  g_vl);

    const int smem_gemm = 3 * STG_BYTES;
    cudaFuncSetAttribute(gemm_mma, cudaFuncAttributeMaxDynamicSharedMemorySize,
                         smem_gemm);
    cudaFuncSetAttribute(attn_mma, cudaFuncAttributeMaxDynamicSharedMemorySize,
                         ATT_SMEM);

    dim3 blk(256);

    // conversions
    cvt_split<<<(BL * DD / 4 + 255) / 256, blk>>>(x, xhi, xlo, BL * DD / 4);
    cvt_transpose<<<dim3(DD / 32, DD / 32), blk>>>(Wq, wqh, wql, DD, DD);
    cvt_transpose<<<dim3(256 / 32, DD / 32), blk>>>(Wk, wkvh, wkvl, DD, 256);
    cvt_transpose<<<dim3(256 / 32, DD / 32), blk>>>(
        Wv, wkvh + 256 * DD, wkvl + 256 * DD, DD, 256);
    cvt_transpose<<<dim3(DD / 32, DD / 32), blk>>>(Wo, woh, wol, DD, DD);

    // projections (tensor cores)
    gemm_mma<<<dim3(DD / 128, BL / 128), blk, smem_gemm>>>(
        xhi, xlo, wqh, wql, pq, DD, DD);
    gemm_mma<<<dim3(512 / 128, BL / 128), blk, smem_gemm>>>(
        xhi, xlo, wkvh, wkvl, pkv, DD, 512);

    // RoPE + split to bf16 hi/lo
    {
        int total = BL * (HH + 2 * KVH) * 32;
        rope_split<<<(total + 255) / 256, blk>>>(pq, pkv, aqh, aql, akh, akl,
                                                 avh, avl);
    }

    // tensor-core attention
    attn_mma<<<dim3(LL / 128, HH, BB), blk, ATT_SMEM>>>(
        aqh, aql, akh, akl, avh, avl, pctx);

    // output projection
    cvt_split<<<(BL * DD / 4 + 255) / 256, blk>>>(pctx, cthi, ctlo, BL * DD / 4);
    gemm_mma<<<dim3(DD / 128, BL / 128), blk, smem_gemm>>>(
        cthi, ctlo, woh, wol, out, DD, DD);
}

// round 6
// speedup vs baseline: 8.0184x; 1.0496x over previous
#include <cuda_runtime.h>
#include <cuda_bf16.h>
#include <math.h>
#include <stdint.h>

// Problem constants
#define BB   2
#define LL   2048
#define DD   1024
#define HH   16
#define KVH  4
#define HDIM 64
#define BL   (BB * LL)    // 4096

typedef unsigned long long ull;

// ---------------------------------------------------------------------------
// mma.sync / ldmatrix / cp.async helpers (baseline PTX ISA)
// ---------------------------------------------------------------------------
__device__ __forceinline__ uint32_t smem_u32(const void* p) {
    uint32_t a;
    asm("{ .reg .u64 t; cvta.to.shared.u64 t, %1; cvt.u32.u64 %0, t; }"
        : "=r"(a) : "l"(p));
    return a;
}
__device__ __forceinline__ void ldsm4(uint32_t addr, uint32_t* r) {
    asm volatile("ldmatrix.sync.aligned.m8n8.x4.shared.b16 {%0,%1,%2,%3}, [%4];"
                 : "=r"(r[0]), "=r"(r[1]), "=r"(r[2]), "=r"(r[3]) : "r"(addr));
}
__device__ __forceinline__ void ldsm4t(uint32_t addr, uint32_t* r) {
    asm volatile("ldmatrix.sync.aligned.m8n8.x4.trans.shared.b16 {%0,%1,%2,%3}, [%4];"
                 : "=r"(r[0]), "=r"(r[1]), "=r"(r[2]), "=r"(r[3]) : "r"(addr));
}
__device__ __forceinline__ void mma16816(float* d, const uint32_t* a,
                                         const uint32_t* b) {
    asm volatile(
        "mma.sync.aligned.m16n8k16.row.col.f32.bf16.bf16.f32 "
        "{%0,%1,%2,%3}, {%4,%5,%6,%7}, {%8,%9}, {%0,%1,%2,%3};"
        : "+f"(d[0]), "+f"(d[1]), "+f"(d[2]), "+f"(d[3])
        : "r"(a[0]), "r"(a[1]), "r"(a[2]), "r"(a[3]), "r"(b[0]), "r"(b[1]));
}
__device__ __forceinline__ void cp16(uint32_t dst, const void* src) {
    asm volatile("cp.async.cg.shared.global [%0], [%1], 16;"
                 :: "r"(dst), "l"(src) : "memory");
}
#define CP_COMMIT() asm volatile("cp.async.commit_group;" ::: "memory")
#define CP_WAIT1()  asm volatile("cp.async.wait_group 1;" ::: "memory")
#define CP_WAIT0()  asm volatile("cp.async.wait_group 0;" ::: "memory")

__device__ __forceinline__ uint32_t packbf(float lo, float hi) {
    __nv_bfloat162 t = __floats2bfloat162_rn(lo, hi);
    return *(uint32_t*)&t;
}
__device__ __forceinline__ float bfhi(float v) {
    return __bfloat162float(__float2bfloat16(v));
}

// ---------------------------------------------------------------------------
// Scratch (__device__ globals — no allocations allowed)
// ---------------------------------------------------------------------------
__device__ float g_q[BL * HH * HDIM];       // [4096][1024] fp32
__device__ float g_kv[BL * 512];            // [4096][512] fp32 (K|V)
__device__ float g_ctx[BL * HH * HDIM];

__device__ __nv_bfloat16 g_xhi[BL * DD];
__device__ __nv_bfloat16 g_xlo[BL * DD];
__device__ __nv_bfloat16 g_ctxhi[BL * DD];
__device__ __nv_bfloat16 g_ctxlo[BL * DD];
__device__ __nv_bfloat16 g_wqt_h[DD * DD];
__device__ __nv_bfloat16 g_wqt_l[DD * DD];
__device__ __nv_bfloat16 g_wkvt_h[512 * DD];
__device__ __nv_bfloat16 g_wkvt_l[512 * DD];
__device__ __nv_bfloat16 g_wot_h[DD * DD];
__device__ __nv_bfloat16 g_wot_l[DD * DD];

// roped + split Q/K/V for tensor-core attention
__device__ __nv_bfloat16 g_qh[BL * DD];     // [4096][1024]
__device__ __nv_bfloat16 g_ql[BL * DD];
__device__ __nv_bfloat16 g_kh[BL * 256];    // [4096][256]
__device__ __nv_bfloat16 g_kl[BL * 256];
__device__ __nv_bfloat16 g_vh[BL * 256];
__device__ __nv_bfloat16 g_vl[BL * 256];

// ---------------------------------------------------------------------------
// fp32 -> bf16 hi/lo split
// ---------------------------------------------------------------------------
__global__ __launch_bounds__(256)
void cvt_split(const float* __restrict__ in, __nv_bfloat16* __restrict__ hi,
               __nv_bfloat16* __restrict__ lo, int n4) {
    int i = blockIdx.x * 256 + threadIdx.x;
    if (i >= n4) return;
    float4 v = ((const float4*)in)[i];
    float vv[4] = {v.x, v.y, v.z, v.w};
    __nv_bfloat16 h[4], l[4];
#pragma unroll
    for (int j = 0; j < 4; j++) {
        h[j] = __float2bfloat16(vv[j]);
        l[j] = __float2bfloat16(vv[j] - __bfloat162float(h[j]));
    }
    ((uint64_t*)hi)[i] = *(uint64_t*)h;
    ((uint64_t*)lo)[i] = *(uint64_t*)l;
}

// ---------------------------------------------------------------------------
// W [K,N] fp32 -> W^T hi/lo bf16 [N,K]
// ---------------------------------------------------------------------------
__global__ __launch_bounds__(256)
void cvt_transpose(const float* __restrict__ W, __nv_bfloat16* __restrict__ hiT,
                   __nv_bfloat16* __restrict__ loT, int Kd, int Nd) {
    __shared__ float t[32][33];
    int n0 = blockIdx.x << 5, k0 = blockIdx.y << 5;
    int tx = threadIdx.x & 31, ty = threadIdx.x >> 5;
    for (int r = ty; r < 32; r += 8)
        t[r][tx] = W[(size_t)(k0 + r) * Nd + n0 + tx];
    __syncthreads();
    for (int r = ty; r < 32; r += 8) {
        float v = t[tx][r];
        __nv_bfloat16 h = __float2bfloat16(v);
        size_t o = (size_t)(n0 + r) * Kd + k0 + tx;
        hiT[o] = h;
        loT[o] = __float2bfloat16(v - __bfloat162float(h));
    }
}

// ---------------------------------------------------------------------------
// Tensor-core GEMM (mma.sync bf16x3): 2-stage cp.async pipeline, occ 2.
// ---------------------------------------------------------------------------
#define STG_BYTES 40960
#define SUB_BYTES 10240

__global__ __launch_bounds__(256, 2)
void gemm_mma(const __nv_bfloat16* __restrict__ Ahi,
              const __nv_bfloat16* __restrict__ Alo,
              const __nv_bfloat16* __restrict__ Bhi,
              const __nv_bfloat16* __restrict__ Blo,
              float* __restrict__ C, int K, int ldc) {
    extern __shared__ char sm[];
    const uint32_t smb = smem_u32(sm);

    const int tid = threadIdx.x;
    const int lid = tid & 31;
    const int wid = tid >> 5;
    const int wm  = wid >> 1;
    const int wn  = wid & 1;
    const int row0 = blockIdx.y << 7;
    const int col0 = blockIdx.x << 7;
    const int NCH = K >> 5;

    const __nv_bfloat16* srcbase[4] = {Ahi, Alo, Bhi, Blo};

    auto prefetch = [&](int c, int stage) {
#pragma unroll
        for (int it = 0; it < 8; it++) {
            int i = tid + (it << 8);
            int s = i >> 9;
            int j = i & 511;
            int r = j >> 2;
            int u = j & 3;
            int grow = (s < 2 ? row0 : col0) + r;
            const __nv_bfloat16* src =
                srcbase[s] + (size_t)grow * K + (c << 5) + (u << 3);
            uint32_t dst = smb + stage * STG_BYTES + s * SUB_BYTES
                         + r * 80 + (u << 4);
            cp16(dst, src);
        }
    };

    prefetch(0, 0); CP_COMMIT();
    prefetch(1, 1); CP_COMMIT();

    float acc[2][8][4];
#pragma unroll
    for (int a = 0; a < 2; a++)
#pragma unroll
        for (int b = 0; b < 8; b++)
#pragma unroll
            for (int d = 0; d < 4; d++) acc[a][b][d] = 0.0f;

    const uint32_t aoff = (uint32_t)((wm * 32 + (lid & 15)) * 80
                                     + ((lid >> 4) << 4));
    const uint32_t boff = (uint32_t)((wn * 64 + ((lid >> 4) << 3) + (lid & 7)) * 80
                                     + (((lid >> 3) & 1) << 4));

    for (int c = 0; c < NCH; c++) {
        CP_WAIT1();
        __syncthreads();

        const uint32_t sb = smb + (c & 1) * STG_BYTES;
        const uint32_t sa_h = sb;
        const uint32_t sa_l = sb + SUB_BYTES;
        const uint32_t sb_h = sb + 2 * SUB_BYTES;
        const uint32_t sb_l = sb + 3 * SUB_BYTES;

#pragma unroll
        for (int ks = 0; ks < 2; ks++) {
            uint32_t Ah[2][4], Al[2][4];
            ldsm4(sa_h + aoff + ks * 32, Ah[0]);
            ldsm4(sa_h + aoff + 16 * 80 + ks * 32, Ah[1]);
            ldsm4(sa_l + aoff + ks * 32, Al[0]);
            ldsm4(sa_l + aoff + 16 * 80 + ks * 32, Al[1]);
#pragma unroll
            for (int g = 0; g < 4; g++) {
                uint32_t Bh[4], Bl[4];
                ldsm4(sb_h + boff + g * (16 * 80) + ks * 32, Bh);
                ldsm4(sb_l + boff + g * (16 * 80) + ks * 32, Bl);
#pragma unroll
                for (int mi = 0; mi < 2; mi++) {
                    mma16816(acc[mi][2 * g],     Ah[mi], Bh);
                    mma16816(acc[mi][2 * g],     Ah[mi], Bl);
                    mma16816(acc[mi][2 * g],     Al[mi], Bh);
                    mma16816(acc[mi][2 * g + 1], Ah[mi], Bh + 2);
                    mma16816(acc[mi][2 * g + 1], Ah[mi], Bl + 2);
                    mma16816(acc[mi][2 * g + 1], Al[mi], Bh + 2);
                }
            }
        }
        __syncthreads();
        if (c + 2 < NCH) prefetch(c + 2, c & 1);
        CP_COMMIT();
    }

#pragma unroll
    for (int mi = 0; mi < 2; mi++) {
        int r0 = row0 + wm * 32 + mi * 16 + (lid >> 2);
#pragma unroll
        for (int ni = 0; ni < 8; ni++) {
            int cc = col0 + wn * 64 + ni * 8 + ((lid & 3) << 1);
            float2 v0; v0.x = acc[mi][ni][0]; v0.y = acc[mi][ni][1];
            float2 v1; v1.x = acc[mi][ni][2]; v1.y = acc[mi][ni][3];
            *(float2*)(C + (size_t)r0 * ldc + cc)       = v0;
            *(float2*)(C + (size_t)(r0 + 8) * ldc + cc) = v1;
        }
    }
}

// ---------------------------------------------------------------------------
// RoPE + hi/lo split
// ---------------------------------------------------------------------------
__global__ __launch_bounds__(256)
void rope_split(const float* __restrict__ q, const float* __restrict__ kv,
                __nv_bfloat16* __restrict__ qh, __nv_bfloat16* __restrict__ ql,
                __nv_bfloat16* __restrict__ kh, __nv_bfloat16* __restrict__ kl,
                __nv_bfloat16* __restrict__ vh, __nv_bfloat16* __restrict__ vl) {
    const int TQ = BL * HH * 32;
    const int TK = BL * KVH * 32;
    const int TV = BL * KVH * 32;
    int idx = blockIdx.x * 256 + threadIdx.x;
    if (idx < TQ + TK) {
        const float* base;
        size_t o;
        __nv_bfloat16 *dh, *dl;
        int j, pos;
        if (idx < TQ) {
            j = idx & 31;
            int t = idx >> 5;
            int token = t >> 4, h = t & 15;
            pos = token & (LL - 1);
            base = q + ((size_t)t << 6);
            o = (size_t)token * 1024 + h * 64 + j;
            dh = qh; dl = ql;
        } else {
            int id2 = idx - TQ;
            j = id2 & 31;
            int t = id2 >> 5;
            int token = t >> 2, kvh2 = t & 3;
            pos = token & (LL - 1);
            base = kv + (size_t)token * 512 + kvh2 * 64;
            o = (size_t)token * 256 + kvh2 * 64 + j;
            dh = kh; dl = kl;
        }
        float inv = powf(10000.0f, -(float)j * (1.0f / 32.0f));
        float ang = (float)pos * inv;
        float s, c;
        sincosf(ang, &s, &c);
        float x1 = base[j], x2 = base[j + 32];
        float y1 = x1 * c - x2 * s;
        float y2 = x2 * c + x1 * s;
        __nv_bfloat16 h1 = __float2bfloat16(y1);
        __nv_bfloat16 h2 = __float2bfloat16(y2);
        dh[o]      = h1;
        dh[o + 32] = h2;
        dl[o]      = __float2bfloat16(y1 - __bfloat162float(h1));
        dl[o + 32] = __float2bfloat16(y2 - __bfloat162float(h2));
    } else if (idx < TQ + TK + TV) {
        int id2 = idx - TQ - TK;
        int j = id2 & 31;
        int t = id2 >> 5;
        int token = t >> 2, kvh2 = t & 3;
        const float* base = kv + (size_t)token * 512 + 256 + kvh2 * 64;
        size_t o = (size_t)token * 256 + kvh2 * 64 + j;
        float x1 = base[j], x2 = base[j + 32];
        __nv_bfloat16 h1 = __float2bfloat16(x1);
        __nv_bfloat16 h2 = __float2bfloat16(x2);
        vh[o]      = h1;
        vh[o + 32] = h2;
        vl[o]      = __float2bfloat16(x1 - __bfloat162float(h1));
        vl[o + 32] = __float2bfloat16(x2 - __bfloat162float(h2));
    }
}

// ---------------------------------------------------------------------------
// Tensor-core flash attention v2: 256 q-rows/CTA, 8 warps x 32 rows
// (two m16 blocks/warp). K/V fragments ldsm'd once per tile, shared by
// both blocks -> MMA-bound. Q staged through KV buffers, frags in regs.
// grid (8, 16, 2), 256 thr, 73.7KB smem, 2-stage KV cp.async pipeline.
// ---------------------------------------------------------------------------
#define AST 144
#define KVSUB (64 * AST)           // 9216
#define KVSTG (4 * KVSUB)          // 36864
#define QSUB  KVSTG                // 36864 = 256 rows * 144B
#define ATT_SMEM (2 * KVSTG)       // 73728

__global__ __launch_bounds__(256, 1)
void attn_mma(const __nv_bfloat16* __restrict__ qh, const __nv_bfloat16* __restrict__ ql,
              const __nv_bfloat16* __restrict__ kh, const __nv_bfloat16* __restrict__ kl,
              const __nv_bfloat16* __restrict__ vh, const __nv_bfloat16* __restrict__ vl,
              float* __restrict__ ctx) {
    extern __shared__ char sm[];
    const uint32_t smb = smem_u32(sm);

    const int tid = threadIdx.x;
    const int lid = tid & 31;
    const int wid = tid >> 5;
    const int q0  = blockIdx.x << 8;           // 256-row q tile
    const int h   = blockIdx.y;
    const int b   = blockIdx.z;
    const int kvh2 = h >> 2;

    const float slope = exp2f(-0.5f * (float)(h + 1));
    const float scale = 0.125f;

    // ---- stage Q (hi at 0, lo at QSUB) through the KV buffer region ----
#pragma unroll
    for (int t = 0; t < 16; t++) {
        int i = tid + (t << 8);
        int s = i >> 11;
        int j = i & 2047;
        int r = j >> 3;
        int u = j & 7;
        const __nv_bfloat16* src =
            (s ? ql : qh) + (size_t)(b * LL + q0 + r) * 1024 + h * 64 + (u << 3);
        cp16(smb + s * QSUB + r * AST + (u << 4), src);
    }
    CP_COMMIT();
    CP_WAIT0();
    __syncthreads();

    // ---- Q fragments for both 16-row blocks -> registers ----
    uint32_t AQh[2][4][4], AQl[2][4][4];
#pragma unroll
    for (int bl = 0; bl < 2; bl++) {
        uint32_t qaddr = (uint32_t)((wid * 32 + bl * 16 + (lid & 15)) * AST
                                    + ((lid >> 4) << 4));
#pragma unroll
        for (int kt = 0; kt < 4; kt++) {
            ldsm4(smb + qaddr + kt * 32, AQh[bl][kt]);
            ldsm4(smb + QSUB + qaddr + kt * 32, AQl[bl][kt]);
        }
    }
    __syncthreads();   // all warps done reading Q before KV overwrites

    // ---- KV pipeline ----
    const __nv_bfloat16* kvsrc[4] = {kh, kl, vh, vl};
    auto pf = [&](int c, int st) {
#pragma unroll
        for (int t = 0; t < 8; t++) {
            int i = tid + (t << 8);
            int s = i >> 9;
            int j = i & 511;
            int r = j >> 3;
            int u = j & 7;
            const __nv_bfloat16* src =
                kvsrc[s] + (size_t)(b * LL + (c << 6) + r) * 256 + kvh2 * 64 + (u << 3);
            cp16(smb + st * KVSTG + s * KVSUB + r * AST + (u << 4), src);
        }
    };
    pf(0, 0); CP_COMMIT();
    pf(1, 1); CP_COMMIT();

    const uint32_t kaddr = (uint32_t)((((lid >> 4) << 3) + (lid & 7)) * AST
                                      + (((lid >> 3) & 1) << 4));
    const uint32_t vaddr = (uint32_t)((lid & 15) * AST + ((lid >> 4) << 4));

    float o[2][8][4];
    float m[2][2], lsum[2][2];
#pragma unroll
    for (int bl = 0; bl < 2; bl++) {
#pragma unroll
        for (int i = 0; i < 8; i++)
#pragma unroll
            for (int e = 0; e < 4; e++) o[bl][i][e] = 0.0f;
        m[bl][0] = -1e30f; m[bl][1] = -1e30f;
        lsum[bl][0] = 0.0f; lsum[bl][1] = 0.0f;
    }

    const int NTILES = LL / 64;   // 32

    for (int c = 0; c < NTILES; c++) {
        CP_WAIT1();
        __syncthreads();

        const uint32_t sb  = smb + (c & 1) * KVSTG;
        const uint32_t skh = sb;
        const uint32_t skl = sb + KVSUB;
        const uint32_t svh = sb + 2 * KVSUB;
        const uint32_t svl = sb + 3 * KVSUB;

        // ---- S = Q.K^T for both blocks; K frags loaded once ----
        float S[2][8][4];
#pragma unroll
        for (int bl = 0; bl < 2; bl++)
#pragma unroll
            for (int i = 0; i < 8; i++)
#pragma unroll
                for (int e = 0; e < 4; e++) S[bl][i][e] = 0.0f;

#pragma unroll
        for (int g = 0; g < 4; g++) {
#pragma unroll
            for (int ks = 0; ks < 4; ks++) {
                uint32_t Bh[4], Bl[4];
                uint32_t base = (g << 4) * AST + kaddr + (ks << 5);
                ldsm4(skh + base, Bh);
                ldsm4(skl + base, Bl);
#pragma unroll
                for (int bl = 0; bl < 2; bl++) {
                    mma16816(S[bl][2 * g],     AQh[bl][ks], Bh);
                    mma16816(S[bl][2 * g],     AQh[bl][ks], Bl);
                    mma16816(S[bl][2 * g],     AQl[bl][ks], Bh);
                    mma16816(S[bl][2 * g + 1], AQh[bl][ks], Bh + 2);
                    mma16816(S[bl][2 * g + 1], AQh[bl][ks], Bl + 2);
                    mma16816(S[bl][2 * g + 1], AQl[bl][ks], Bh + 2);
                }
            }
        }

        // ---- softmax per block, P -> A-fragments ----
        uint32_t PAh[2][4][4], PAl[2][4][4];
        const float colb = (float)((c << 6) + 2 * (lid & 3));
#pragma unroll
        for (int bl = 0; bl < 2; bl++) {
            const float qrow0 = (float)(q0 + wid * 32 + bl * 16 + (lid >> 2));
            const float qrow1 = qrow0 + 8.0f;
            const float sb0 = slope * (colb - qrow0);
            const float sb1 = slope * (colb - qrow1);
            float mx0 = -1e30f, mx1 = -1e30f;
#pragma unroll
            for (int nt = 0; nt < 8; nt++) {
                float bo = slope * (float)(nt << 3);
                S[bl][nt][0] = fmaf(S[bl][nt][0], scale, sb0 + bo);
                S[bl][nt][1] = fmaf(S[bl][nt][1], scale, sb0 + bo + slope);
                S[bl][nt][2] = fmaf(S[bl][nt][2], scale, sb1 + bo);
                S[bl][nt][3] = fmaf(S[bl][nt][3], scale, sb1 + bo + slope);
                mx0 = fmaxf(mx0, fmaxf(S[bl][nt][0], S[bl][nt][1]));
                mx1 = fmaxf(mx1, fmaxf(S[bl][nt][2], S[bl][nt][3]));
            }
            mx0 = fmaxf(mx0, __shfl_xor_sync(0xffffffffu, mx0, 1));
            mx0 = fmaxf(mx0, __shfl_xor_sync(0xffffffffu, mx0, 2));
            mx1 = fmaxf(mx1, __shfl_xor_sync(0xffffffffu, mx1, 1));
            mx1 = fmaxf(mx1, __shfl_xor_sync(0xffffffffu, mx1, 2));

            float mn0 = fmaxf(m[bl][0], mx0);
            float mn1 = fmaxf(m[bl][1], mx1);
            float corr0 = __expf(m[bl][0] - mn0);
            float corr1 = __expf(m[bl][1] - mn1);
            m[bl][0] = mn0; m[bl][1] = mn1;

            float ps0 = 0.0f, ps1 = 0.0f;
#pragma unroll
            for (int nt = 0; nt < 8; nt++) {
                S[bl][nt][0] = __expf(S[bl][nt][0] - mn0);
                S[bl][nt][1] = __expf(S[bl][nt][1] - mn0);
                S[bl][nt][2] = __expf(S[bl][nt][2] - mn1);
                S[bl][nt][3] = __expf(S[bl][nt][3] - mn1);
                ps0 += S[bl][nt][0] + S[bl][nt][1];
                ps1 += S[bl][nt][2] + S[bl][nt][3];
            }
            ps0 += __shfl_xor_sync(0xffffffffu, ps0, 1);
            ps0 += __shfl_xor_sync(0xffffffffu, ps0, 2);
            ps1 += __shfl_xor_sync(0xffffffffu, ps1, 1);
            ps1 += __shfl_xor_sync(0xffffffffu, ps1, 2);
            lsum[bl][0] = lsum[bl][0] * corr0 + ps0;
            lsum[bl][1] = lsum[bl][1] * corr1 + ps1;

#pragma unroll
            for (int nt = 0; nt < 8; nt++) {
                o[bl][nt][0] *= corr0;
                o[bl][nt][1] *= corr0;
                o[bl][nt][2] *= corr1;
                o[bl][nt][3] *= corr1;
            }

#pragma unroll
            for (int kt = 0; kt < 4; kt++) {
                float p00 = S[bl][2 * kt][0],     p01 = S[bl][2 * kt][1];
                float p02 = S[bl][2 * kt][2],     p03 = S[bl][2 * kt][3];
                float p10 = S[bl][2 * kt + 1][0], p11 = S[bl][2 * kt + 1][1];
                float p12 = S[bl][2 * kt + 1][2], p13 = S[bl][2 * kt + 1][3];
                float h00 = bfhi(p00), h01 = bfhi(p01), h02 = bfhi(p02), h03 = bfhi(p03);
                float h10 = bfhi(p10), h11 = bfhi(p11), h12 = bfhi(p12), h13 = bfhi(p13);
                PAh[bl][kt][0] = packbf(h00, h01);
                PAh[bl][kt][1] = packbf(h02, h03);
                PAh[bl][kt][2] = packbf(h10, h11);
                PAh[bl][kt][3] = packbf(h12, h13);
                PAl[bl][kt][0] = packbf(p00 - h00, p01 - h01);
                PAl[bl][kt][1] = packbf(p02 - h02, p03 - h03);
                PAl[bl][kt][2] = packbf(p10 - h10, p11 - h11);
                PAl[bl][kt][3] = packbf(p12 - h12, p13 - h13);
            }
        }

        // ---- O += P @ V; V frags loaded once, shared by both blocks ----
#pragma unroll
        for (int dg = 0; dg < 4; dg++) {
#pragma unroll
            for (int kt = 0; kt < 4; kt++) {
                uint32_t Bvh[4], Bvl[4];
                uint32_t base = (kt << 4) * AST + vaddr + (dg << 5);
                ldsm4t(svh + base, Bvh);
                ldsm4t(svl + base, Bvl);
#pragma unroll
                for (int bl = 0; bl < 2; bl++) {
                    mma16816(o[bl][2 * dg],     PAh[bl][kt], Bvh);
                    mma16816(o[bl][2 * dg],     PAh[bl][kt], Bvl);
                    mma16816(o[bl][2 * dg],     PAl[bl][kt], Bvh);
                    mma16816(o[bl][2 * dg + 1], PAh[bl][kt], Bvh + 2);
                    mma16816(o[bl][2 * dg + 1], PAh[bl][kt], Bvl + 2);
                    mma16816(o[bl][2 * dg + 1], PAl[bl][kt], Bvh + 2);
                }
            }
        }

        __syncthreads();
        if (c + 2 < NTILES) pf(c + 2, c & 1);
        CP_COMMIT();
    }

    // ---- epilogue ----
#pragma unroll
    for (int bl = 0; bl < 2; bl++) {
        float inv0 = 1.0f / lsum[bl][0];
        float inv1 = 1.0f / lsum[bl][1];
        const int r0 = b * LL + q0 + wid * 32 + bl * 16 + (lid >> 2);
#pragma unroll
        for (int nt = 0; nt < 8; nt++) {
            int cc = h * 64 + nt * 8 + ((lid & 3) << 1);
            float2 v0; v0.x = o[bl][nt][0] * inv0; v0.y = o[bl][nt][1] * inv0;
            float2 v1; v1.x = o[bl][nt][2] * inv1; v1.y = o[bl][nt][3] * inv1;
            *(float2*)(ctx + (size_t)r0 * 1024 + cc)       = v0;
            *(float2*)(ctx + (size_t)(r0 + 8) * 1024 + cc) = v1;
        }
    }
}

// ---------------------------------------------------------------------------
// kernel_launch
// ---------------------------------------------------------------------------
extern "C" void kernel_launch(void* const* d_in, const int* in_sizes, int n_in,
                              void* d_out, int out_size) {
    const float* x  = (const float*)d_in[0];
    const float* Wq = (const float*)d_in[1];
    const float* Wk = (const float*)d_in[2];
    const float* Wv = (const float*)d_in[3];
    const float* Wo = (const float*)d_in[4];
    float* out = (float*)d_out;

    float *pq, *pkv, *pctx;
    cudaGetSymbolAddress((void**)&pq,   g_q);
    cudaGetSymbolAddress((void**)&pkv,  g_kv);
    cudaGetSymbolAddress((void**)&pctx, g_ctx);

    __nv_bfloat16 *xhi, *xlo, *cthi, *ctlo;
    __nv_bfloat16 *wqh, *wql, *wkvh, *wkvl, *woh, *wol;
    __nv_bfloat16 *aqh, *aql, *akh, *akl, *avh, *avl;
    cudaGetSymbolAddress((void**)&xhi,  g_xhi);
    cudaGetSymbolAddress((void**)&xlo,  g_xlo);
    cudaGetSymbolAddress((void**)&cthi, g_ctxhi);
    cudaGetSymbolAddress((void**)&ctlo, g_ctxlo);
    cudaGetSymbolAddress((void**)&wqh,  g_wqt_h);
    cudaGetSymbolAddress((void**)&wql,  g_wqt_l);
    cudaGetSymbolAddress((void**)&wkvh, g_wkvt_h);
    cudaGetSymbolAddress((void**)&wkvl, g_wkvt_l);
    cudaGetSymbolAddress((void**)&woh,  g_wot_h);
    cudaGetSymbolAddress((void**)&wol,  g_wot_l);
    cudaGetSymbolAddress((void**)&aqh,  g_qh);
    cudaGetSymbolAddress((void**)&aql,  g_ql);
    cudaGetSymbolAddress((void**)&akh,  g_kh);
    cudaGetSymbolAddress((void**)&akl,  g_kl);
    cudaGetSymbolAddress((void**)&avh,  g_vh);
    cudaGetSymbolAddress((void**)&avl,  g_vl);

    const int smem_gemm = 2 * STG_BYTES;   // 81920
    cudaFuncSetAttribute(gemm_mma, cudaFuncAttributeMaxDynamicSharedMemorySize,
                         smem_gemm);
    cudaFuncSetAttribute(attn_mma, cudaFuncAttributeMaxDynamicSharedMemorySize,
                         ATT_SMEM);

    dim3 blk(256);

    // conversions
    cvt_split<<<(BL * DD / 4 + 255) / 256, blk>>>(x, xhi, xlo, BL * DD / 4);
    cvt_transpose<<<dim3(DD / 32, DD / 32), blk>>>(Wq, wqh, wql, DD, DD);
    cvt_transpose<<<dim3(256 / 32, DD / 32), blk>>>(Wk, wkvh, wkvl, DD, 256);
    cvt_transpose<<<dim3(256 / 32, DD / 32), blk>>>(
        Wv, wkvh + 256 * DD, wkvl + 256 * DD, DD, 256);
    cvt_transpose<<<dim3(DD / 32, DD / 32), blk>>>(Wo, woh, wol, DD, DD);

    // projections (tensor cores)
    gemm_mma<<<dim3(DD / 128, BL / 128), blk, smem_gemm>>>(
        xhi, xlo, wqh, wql, pq, DD, DD);
    gemm_mma<<<dim3(512 / 128, BL / 128), blk, smem_gemm>>>(
        xhi, xlo, wkvh, wkvl, pkv, DD, 512);

    // RoPE + split to bf16 hi/lo
    {
        int total = BL * (HH + 2 * KVH) * 32;
        rope_split<<<(total + 255) / 256, blk>>>(pq, pkv, aqh, aql, akh, akl,
                                                 avh, avl);
    }

    // tensor-core attention (256-row q tiles)
    attn_mma<<<dim3(LL / 256, HH, BB), blk, ATT_SMEM>>>(
        aqh, aql, akh, akl, avh, avl, pctx);

    // output projection
    cvt_split<<<(BL * DD / 4 + 255) / 256, blk>>>(pctx, cthi, ctlo, BL * DD / 4);
    gemm_mma<<<dim3(DD / 128, BL / 128), blk, smem_gemm>>>(
        cthi, ctlo, woh, wol, out, DD, DD);
}